// round 2
// baseline (speedup 1.0000x reference)
#include <cuda_runtime.h>

#define NN 100000
#define EE 1600000
#define GG 1024

// -------------------- device scratch (no allocation allowed) --------------------
__device__ float g_A[(size_t)NN * 64];
__device__ float g_B[(size_t)NN * 64];
__device__ float g_C[(size_t)NN * 64];
__device__ float g_xpad[(size_t)NN * 16];
__device__ float g_stats[128];
__device__ float g_ss[128];
__device__ float g_pool[GG * 64];
__device__ float g_cnt[GG];

// Vectorized global reduction (sm_90+): one RED.128 instead of 4 scalar atomics.
__device__ __forceinline__ void red_add_f4(float* addr, float x, float y, float z, float w) {
    asm volatile("{ .reg .u64 p; cvta.to.global.u64 p, %0;\n\t"
                 "red.global.add.v4.f32 [p], {%1,%2,%3,%4}; }\n"
                 :: "l"(addr), "f"(x), "f"(y), "f"(z), "f"(w) : "memory");
}

// -------------------- prep --------------------
__global__ void make_xpad(const float* __restrict__ x, float* __restrict__ xp) {
    int i = blockIdx.x * blockDim.x + threadIdx.x;
    if (i < NN * 16) { int n = i >> 4, c = i & 15; xp[i] = (c < 9) ? x[n * 9 + c] : 0.f; }
}

// -------------------- edge aggregation --------------------
// Layer 0: 9 input features padded to 16; 3 float4 groups per edge (cols 0..11).
__global__ void agg_scatter16(const float* __restrict__ h, const int* __restrict__ src,
                              const int* __restrict__ dst, const float* __restrict__ ew,
                              float* agg) {
    int i = blockIdx.x * blockDim.x + threadIdx.x;
    if (i >= EE * 3) return;
    int e = i / 3, v = i - e * 3;
    int s = src[e], d = dst[e];
    float w = ew[e];
    const float4 hv = *(const float4*)&h[(size_t)s * 16 + v * 4];
    red_add_f4(&agg[(size_t)d * 16 + v * 4], hv.x * w, hv.y * w, hv.z * w, hv.w * w);
}

// Layers 1,2: 64 features; 16 float4 groups per edge.
__global__ void agg_scatter64(const float* __restrict__ h, const int* __restrict__ src,
                              const int* __restrict__ dst, const float* __restrict__ ew,
                              float* agg) {
    int i = blockIdx.x * blockDim.x + threadIdx.x;
    if (i >= EE * 16) return;
    int e = i >> 4, v = i & 15;
    int s = src[e], d = dst[e];
    float w = ew[e];
    const float4 hv = *(const float4*)&h[(size_t)s * 64 + v * 4];
    red_add_f4(&agg[(size_t)d * 64 + v * 4], hv.x * w, hv.y * w, hv.z * w, hv.w * w);
}

// -------------------- fused node update: out = agg@W_rel + x@W_root + b (+ BN stats) ----
// Block = 128 threads, tile = 64 nodes x 64 features; each thread: 4 nodes x 8 features.
template <int K, int ST, bool STATS>
__global__ void __launch_bounds__(128) node_update(
    const float* __restrict__ Ag, const float* __restrict__ Xin,
    const float* __restrict__ Wrel, const float* __restrict__ Wroot,
    const float* __restrict__ bias, float* __restrict__ Out, float* stats) {
    constexpr int PAD = (ST == 64) ? 65 : 17;   // avoid bank conflicts on per-node reads
    constexpr int C4 = ST / 4;
    extern __shared__ float sm[];
    float* sA   = sm;                // 64*PAD
    float* sX   = sA + 64 * PAD;     // 64*PAD
    float* sWr  = sX + 64 * PAD;     // K*64
    float* sWo  = sWr + K * 64;      // K*64
    float* sSum = sWo + K * 64;      // 64
    float* sSq  = sSum + 64;         // 64

    const int tid = threadIdx.x;
    const int base = blockIdx.x * 64;

    // stage weights (row-major [k][f])
    for (int i = tid; i < K * 16; i += 128) {
        ((float4*)sWr)[i] = ((const float4*)Wrel)[i];
        ((float4*)sWo)[i] = ((const float4*)Wroot)[i];
    }
    // stage node rows (agg + input), zero-fill tail nodes
    for (int i = tid; i < 64 * C4; i += 128) {
        int r = i / C4, c = i - r * C4;
        int n = base + r;
        float4 va = make_float4(0.f, 0.f, 0.f, 0.f), vx = va;
        if (n < NN) {
            va = *(const float4*)&Ag[(size_t)n * ST + c * 4];
            vx = *(const float4*)&Xin[(size_t)n * ST + c * 4];
        }
        int o = r * PAD + c * 4;
        sA[o] = va.x; sA[o + 1] = va.y; sA[o + 2] = va.z; sA[o + 3] = va.w;
        sX[o] = vx.x; sX[o + 1] = vx.y; sX[o + 2] = vx.z; sX[o + 3] = vx.w;
    }
    if (STATS && tid < 64) { sSum[tid] = 0.f; sSq[tid] = 0.f; }
    __syncthreads();

    const int fg = (tid & 7) * 8;   // feature base (8 features)
    const int ng = (tid >> 3) * 4;  // node base in tile (4 nodes)

    float acc[4][8];
#pragma unroll
    for (int i = 0; i < 4; i++)
#pragma unroll
        for (int j = 0; j < 8; j++) acc[i][j] = 0.f;

#pragma unroll 4
    for (int k = 0; k < K; ++k) {
        float a[4], xv[4];
#pragma unroll
        for (int i = 0; i < 4; i++) {
            a[i]  = sA[(ng + i) * PAD + k];
            xv[i] = sX[(ng + i) * PAD + k];
        }
        float wr[8], wo[8];
        *(float4*)&wr[0] = *(const float4*)&sWr[k * 64 + fg];
        *(float4*)&wr[4] = *(const float4*)&sWr[k * 64 + fg + 4];
        *(float4*)&wo[0] = *(const float4*)&sWo[k * 64 + fg];
        *(float4*)&wo[4] = *(const float4*)&sWo[k * 64 + fg + 4];
#pragma unroll
        for (int i = 0; i < 4; i++)
#pragma unroll
            for (int j = 0; j < 8; j++)
                acc[i][j] = fmaf(xv[i], wo[j], fmaf(a[i], wr[j], acc[i][j]));
    }

    float bz[8];
    *(float4*)&bz[0] = *(const float4*)&bias[fg];
    *(float4*)&bz[4] = *(const float4*)&bias[fg + 4];

    float s[8], q[8];
#pragma unroll
    for (int j = 0; j < 8; j++) { s[j] = 0.f; q[j] = 0.f; }

#pragma unroll
    for (int i = 0; i < 4; i++) {
        int n = base + ng + i;
        if (n < NN) {
            float o[8];
#pragma unroll
            for (int j = 0; j < 8; j++) o[j] = acc[i][j] + bz[j];
            *(float4*)&Out[(size_t)n * 64 + fg]     = make_float4(o[0], o[1], o[2], o[3]);
            *(float4*)&Out[(size_t)n * 64 + fg + 4] = make_float4(o[4], o[5], o[6], o[7]);
            if (STATS) {
#pragma unroll
                for (int j = 0; j < 8; j++) { s[j] += o[j]; q[j] += o[j] * o[j]; }
            }
        }
    }
    if (STATS) {
#pragma unroll
        for (int j = 0; j < 8; j++) {
            atomicAdd(&sSum[fg + j], s[j]);
            atomicAdd(&sSq[fg + j], q[j]);
        }
        __syncthreads();
        if (tid < 64) {
            atomicAdd(&stats[tid], sSum[tid]);
            atomicAdd(&stats[64 + tid], sSq[tid]);
        }
    }
}

// -------------------- batchnorm --------------------
__global__ void bn_finalize(const float* __restrict__ stats, const float* __restrict__ g,
                            const float* __restrict__ be, float* __restrict__ ss) {
    int f = threadIdx.x;
    const float inv = 1.f / (float)NN;
    float m = stats[f] * inv;
    float var = stats[64 + f] * inv - m * m;
    float sc = g[f] * rsqrtf(var + 1e-5f);
    ss[f] = sc;
    ss[64 + f] = fmaf(-m, sc, be[f]);
}

__global__ void bn_apply(float* __restrict__ buf, const float* __restrict__ ss) {
    int i = blockIdx.x * blockDim.x + threadIdx.x;
    if (i >= NN * 16) return;
    int v = i & 15;
    float4 h = ((float4*)buf)[i];
    float4 sc = ((const float4*)ss)[v];
    float4 sh = ((const float4*)ss)[16 + v];
    h.x = fmaxf(fmaf(h.x, sc.x, sh.x), 0.f);
    h.y = fmaxf(fmaf(h.y, sc.y, sh.y), 0.f);
    h.z = fmaxf(fmaf(h.z, sc.z, sh.z), 0.f);
    h.w = fmaxf(fmaf(h.w, sc.w, sh.w), 0.f);
    ((float4*)buf)[i] = h;
}

// -------------------- pooling + head --------------------
__global__ void pool_scatter(const float* __restrict__ h, const int* __restrict__ batch,
                             float* pool, float* cnt) {
    int i = blockIdx.x * blockDim.x + threadIdx.x;
    if (i >= NN * 16) return;
    int n = i >> 4, v = i & 15;
    int b = batch[n];
    float4 hv = ((const float4*)h)[i];
    red_add_f4(&pool[(size_t)b * 64 + v * 4], hv.x, hv.y, hv.z, hv.w);
    if (v == 0) atomicAdd(&cnt[b], 1.f);
}

__global__ void head_kernel(const float* __restrict__ pool, const float* __restrict__ cnt,
                            const float* __restrict__ Wl1, const float* __restrict__ bl1,
                            const float* __restrict__ Wl2, const float* __restrict__ bl2,
                            float* __restrict__ out) {
    __shared__ float sp[64], sz[64];
    int g = blockIdx.x, t = threadIdx.x;
    float c = fmaxf(cnt[g], 1.f);
    sp[t] = pool[g * 64 + t] / c;
    __syncthreads();
    float z = bl1[t];
#pragma unroll 8
    for (int k = 0; k < 64; k++) z = fmaf(sp[k], Wl1[k * 64 + t], z);
    sz[t] = fmaxf(z, 0.f);
    __syncthreads();
    if (t < 6) {
        float o = bl2[t];
#pragma unroll 8
        for (int k = 0; k < 64; k++) o = fmaf(sz[k], Wl2[k * 6 + t], o);
        out[g * 6 + t] = o;
    }
}

// -------------------- launch --------------------
extern "C" void kernel_launch(void* const* d_in, const int* in_sizes, int n_in,
                              void* d_out, int out_size) {
    const float* x     = (const float*)d_in[0];
    const int*   ei    = (const int*)d_in[1];   // int32 on device (harness has no int64 path)
    const float* ew    = (const float*)d_in[2];
    const int*   batch = (const int*)d_in[3];
    const float *Wrel0 = (const float*)d_in[4],  *Wroot0 = (const float*)d_in[5],  *b0 = (const float*)d_in[6];
    const float *Wrel1 = (const float*)d_in[7],  *Wroot1 = (const float*)d_in[8],  *b1 = (const float*)d_in[9];
    const float *Wrel2 = (const float*)d_in[10], *Wroot2 = (const float*)d_in[11], *b2 = (const float*)d_in[12];
    const float *g0 = (const float*)d_in[13], *be0 = (const float*)d_in[14];
    const float *g1 = (const float*)d_in[15], *be1 = (const float*)d_in[16];
    const float *Wl1 = (const float*)d_in[17], *bl1 = (const float*)d_in[18];
    const float *Wl2 = (const float*)d_in[19], *bl2 = (const float*)d_in[20];
    float* out = (float*)d_out;

    const int* src = ei;
    const int* dst = ei + EE;

    float *pA, *pB, *pC, *pX, *pStats, *pSS, *pPool, *pCnt;
    cudaGetSymbolAddress((void**)&pA, g_A);
    cudaGetSymbolAddress((void**)&pB, g_B);
    cudaGetSymbolAddress((void**)&pC, g_C);
    cudaGetSymbolAddress((void**)&pX, g_xpad);
    cudaGetSymbolAddress((void**)&pStats, g_stats);
    cudaGetSymbolAddress((void**)&pSS, g_ss);
    cudaGetSymbolAddress((void**)&pPool, g_pool);
    cudaGetSymbolAddress((void**)&pCnt, g_cnt);

    const int smem64 = (64 * 65 * 2 + 64 * 64 * 2 + 128) * (int)sizeof(float);  // 66560 B
    const int smem9  = (64 * 17 * 2 + 9 * 64 * 2 + 128) * (int)sizeof(float);   // 13824 B
    cudaFuncSetAttribute((const void*)node_update<64, 64, true>,
                         cudaFuncAttributeMaxDynamicSharedMemorySize, smem64);
    cudaFuncSetAttribute((const void*)node_update<64, 64, false>,
                         cudaFuncAttributeMaxDynamicSharedMemorySize, smem64);

    const int NB = (NN + 63) / 64;

    // prep
    make_xpad<<<(NN * 16 + 255) / 256, 256>>>(x, pX);

    // ---- layer 0 (K=9 aggregation space) ----
    cudaMemsetAsync(pA, 0, (size_t)NN * 16 * sizeof(float));
    agg_scatter16<<<(EE * 3 + 255) / 256, 256>>>(pX, src, dst, ew, pA);
    cudaMemsetAsync(pStats, 0, 128 * sizeof(float));
    node_update<9, 16, true><<<NB, 128, smem9>>>(pA, pX, Wrel0, Wroot0, b0, pB, pStats);
    bn_finalize<<<1, 64>>>(pStats, g0, be0, pSS);
    bn_apply<<<(NN * 16 + 255) / 256, 256>>>(pB, pSS);

    // ---- layer 1 ----
    cudaMemsetAsync(pA, 0, (size_t)NN * 64 * sizeof(float));
    agg_scatter64<<<(EE * 16 + 255) / 256, 256>>>(pB, src, dst, ew, pA);
    cudaMemsetAsync(pStats, 0, 128 * sizeof(float));
    node_update<64, 64, true><<<NB, 128, smem64>>>(pA, pB, Wrel1, Wroot1, b1, pC, pStats);
    bn_finalize<<<1, 64>>>(pStats, g1, be1, pSS);
    bn_apply<<<(NN * 16 + 255) / 256, 256>>>(pC, pSS);

    // ---- layer 2 (no BN) ----
    cudaMemsetAsync(pB, 0, (size_t)NN * 64 * sizeof(float));
    agg_scatter64<<<(EE * 16 + 255) / 256, 256>>>(pC, src, dst, ew, pB);
    node_update<64, 64, false><<<NB, 128, smem64>>>(pB, pC, Wrel2, Wroot2, b2, pA, nullptr);

    // ---- pool + head ----
    cudaMemsetAsync(pPool, 0, GG * 64 * sizeof(float));
    cudaMemsetAsync(pCnt, 0, GG * sizeof(float));
    pool_scatter<<<(NN * 16 + 255) / 256, 256>>>(pA, batch, pPool, pCnt);
    head_kernel<<<GG, 64>>>(pPool, pCnt, Wl1, bl1, Wl2, bl2, out);
}

// round 3
// speedup vs baseline: 1.2406x; 1.2406x over previous
#include <cuda_runtime.h>

#define NN 100000
#define EE 1600000
#define GG 1024

// -------------------- device scratch (no allocation allowed) --------------------
__device__ float g_A[(size_t)NN * 64];     // aggregation output
__device__ float g_B[(size_t)NN * 64];     // h1raw, later h3
__device__ float g_C[(size_t)NN * 64];     // h2raw
__device__ float g_xpad[(size_t)NN * 16];
__device__ int   g_off[NN + 1];            // CSR row pointers (by dst)
__device__ int   g_cur[NN];                // placement cursors
__device__ int   g_bsum[128];              // scan block sums
__device__ int2  g_epack[EE];              // (src, weight-bits) sorted by dst
__device__ float g_stats[128];
__device__ float g_ss[128];                // BN scale[64] + shift[64]
__device__ float g_pool[GG * 64];
__device__ float g_cnt[GG];

__device__ __forceinline__ void red_add_f4(float* addr, float x, float y, float z, float w) {
    asm volatile("{ .reg .u64 p; cvta.to.global.u64 p, %0;\n\t"
                 "red.global.add.v4.f32 [p], {%1,%2,%3,%4}; }\n"
                 :: "l"(addr), "f"(x), "f"(y), "f"(z), "f"(w) : "memory");
}

// -------------------- prep --------------------
__global__ void make_xpad(const float* __restrict__ x, float* __restrict__ xp) {
    int i = blockIdx.x * blockDim.x + threadIdx.x;
    if (i < NN * 16) { int n = i >> 4, c = i & 15; xp[i] = (c < 9) ? x[n * 9 + c] : 0.f; }
}

// -------------------- CSR build --------------------
__global__ void hist_kernel(const int* __restrict__ dst, int* __restrict__ off) {
    int e = blockIdx.x * blockDim.x + threadIdx.x;
    if (e < EE) atomicAdd(&off[dst[e] + 1], 1);
}

// inclusive scan, 1024-thread blocks
__global__ void scan1(int* __restrict__ off, int* __restrict__ bsum) {
    __shared__ int ws[32];
    int g = blockIdx.x * 1024 + threadIdx.x;
    int v = (g <= NN) ? off[g] : 0;
    int lane = threadIdx.x & 31;
#pragma unroll
    for (int d = 1; d < 32; d <<= 1) { int t = __shfl_up_sync(~0u, v, d); if (lane >= d) v += t; }
    if (lane == 31) ws[threadIdx.x >> 5] = v;
    __syncthreads();
    if (threadIdx.x < 32) {
        int t = ws[threadIdx.x];
#pragma unroll
        for (int d = 1; d < 32; d <<= 1) { int u = __shfl_up_sync(~0u, t, d); if (threadIdx.x >= d) t += u; }
        ws[threadIdx.x] = t;
    }
    __syncthreads();
    if (threadIdx.x >= 32) v += ws[(threadIdx.x >> 5) - 1];
    if (g <= NN) off[g] = v;
    if (threadIdx.x == 1023) bsum[blockIdx.x] = v;
}

__global__ void scan2(int* __restrict__ bsum, int nb) {
    __shared__ int s[128];
    int t = threadIdx.x;
    s[t] = (t < nb) ? bsum[t] : 0;
    __syncthreads();
    if (t == 0) { int r = 0; for (int i = 0; i < nb; i++) { r += s[i]; s[i] = r; } }
    __syncthreads();
    if (t < nb) bsum[t] = s[t];
}

__global__ void scan3(int* __restrict__ off, const int* __restrict__ bsum, int* __restrict__ cur) {
    int g = blockIdx.x * 1024 + threadIdx.x;
    if (g > NN) return;
    int add = (blockIdx.x == 0) ? 0 : bsum[blockIdx.x - 1];
    int v = off[g] + add;
    if (blockIdx.x > 0) off[g] = v;
    if (g < NN) cur[g] = v;
}

__global__ void place_kernel(const int* __restrict__ src, const int* __restrict__ dst,
                             const float* __restrict__ ew, int* __restrict__ cur,
                             int2* __restrict__ epack) {
    int e = blockIdx.x * blockDim.x + threadIdx.x;
    if (e >= EE) return;
    int p = atomicAdd(&cur[dst[e]], 1);
    epack[p] = make_int2(src[e], __float_as_int(ew[e]));
}

// -------------------- CSR aggregation (gather, register accumulate, one store) ----
// LPN lanes per node, each lane owns one float4 of the row. Optional fused BN+ReLU
// applied to the gathered source rows.
template <int LPN, bool BN>
__global__ void __launch_bounds__(256) agg_csr(
    const float* __restrict__ h, const int* __restrict__ rowptr,
    const int2* __restrict__ epack, const float* __restrict__ ss,
    float* __restrict__ agg) {
    constexpr int NPB = 256 / LPN;
    int node = blockIdx.x * NPB + threadIdx.x / LPN;
    int lane = threadIdx.x % LPN;
    if (node >= NN) return;
    int beg = rowptr[node], end = rowptr[node + 1];
    float4 sc, sh;
    if (BN) { sc = ((const float4*)ss)[lane]; sh = ((const float4*)ss)[16 + lane]; }
    float4 acc = make_float4(0.f, 0.f, 0.f, 0.f);
    for (int i = beg; i < end; ++i) {
        int2 ep = epack[i];
        float w = __int_as_float(ep.y);
        float4 v = ((const float4*)h)[(size_t)ep.x * LPN + lane];
        if (BN) {
            v.x = fmaxf(fmaf(v.x, sc.x, sh.x), 0.f);
            v.y = fmaxf(fmaf(v.y, sc.y, sh.y), 0.f);
            v.z = fmaxf(fmaf(v.z, sc.z, sh.z), 0.f);
            v.w = fmaxf(fmaf(v.w, sc.w, sh.w), 0.f);
        }
        acc.x = fmaf(v.x, w, acc.x);
        acc.y = fmaf(v.y, w, acc.y);
        acc.z = fmaf(v.z, w, acc.z);
        acc.w = fmaf(v.w, w, acc.w);
    }
    ((float4*)agg)[(size_t)node * LPN + lane] = acc;
}

// -------------------- fused node update: out = agg@W_rel + BN?(x)@W_root + b (+ stats) ----
template <int K, int ST, bool STATS, bool BNIN>
__global__ void __launch_bounds__(128) node_update(
    const float* __restrict__ Ag, const float* __restrict__ Xin,
    const float* __restrict__ Wrel, const float* __restrict__ Wroot,
    const float* __restrict__ bias, const float* __restrict__ ss,
    float* __restrict__ Out, float* stats) {
    constexpr int PAD = (ST == 64) ? 65 : 17;
    constexpr int C4 = ST / 4;
    extern __shared__ float sm[];
    float* sA   = sm;
    float* sX   = sA + 64 * PAD;
    float* sWr  = sX + 64 * PAD;
    float* sWo  = sWr + K * 64;
    float* sSum = sWo + K * 64;
    float* sSq  = sSum + 64;

    const int tid = threadIdx.x;
    const int base = blockIdx.x * 64;

    for (int i = tid; i < K * 16; i += 128) {
        ((float4*)sWr)[i] = ((const float4*)Wrel)[i];
        ((float4*)sWo)[i] = ((const float4*)Wroot)[i];
    }
    for (int i = tid; i < 64 * C4; i += 128) {
        int r = i / C4, c = i - r * C4;
        int n = base + r;
        float4 va = make_float4(0.f, 0.f, 0.f, 0.f), vx = va;
        if (n < NN) {
            va = *(const float4*)&Ag[(size_t)n * ST + c * 4];
            vx = *(const float4*)&Xin[(size_t)n * ST + c * 4];
        }
        if (BNIN) {
            float4 sc = ((const float4*)ss)[c], sh = ((const float4*)ss)[16 + c];
            vx.x = fmaxf(fmaf(vx.x, sc.x, sh.x), 0.f);
            vx.y = fmaxf(fmaf(vx.y, sc.y, sh.y), 0.f);
            vx.z = fmaxf(fmaf(vx.z, sc.z, sh.z), 0.f);
            vx.w = fmaxf(fmaf(vx.w, sc.w, sh.w), 0.f);
        }
        int o = r * PAD + c * 4;
        sA[o] = va.x; sA[o + 1] = va.y; sA[o + 2] = va.z; sA[o + 3] = va.w;
        sX[o] = vx.x; sX[o + 1] = vx.y; sX[o + 2] = vx.z; sX[o + 3] = vx.w;
    }
    if (STATS && tid < 64) { sSum[tid] = 0.f; sSq[tid] = 0.f; }
    __syncthreads();

    const int fg = (tid & 7) * 8;
    const int ng = (tid >> 3) * 4;

    float acc[4][8];
#pragma unroll
    for (int i = 0; i < 4; i++)
#pragma unroll
        for (int j = 0; j < 8; j++) acc[i][j] = 0.f;

#pragma unroll 4
    for (int k = 0; k < K; ++k) {
        float a[4], xv[4];
#pragma unroll
        for (int i = 0; i < 4; i++) {
            a[i]  = sA[(ng + i) * PAD + k];
            xv[i] = sX[(ng + i) * PAD + k];
        }
        float wr[8], wo[8];
        *(float4*)&wr[0] = *(const float4*)&sWr[k * 64 + fg];
        *(float4*)&wr[4] = *(const float4*)&sWr[k * 64 + fg + 4];
        *(float4*)&wo[0] = *(const float4*)&sWo[k * 64 + fg];
        *(float4*)&wo[4] = *(const float4*)&sWo[k * 64 + fg + 4];
#pragma unroll
        for (int i = 0; i < 4; i++)
#pragma unroll
            for (int j = 0; j < 8; j++)
                acc[i][j] = fmaf(xv[i], wo[j], fmaf(a[i], wr[j], acc[i][j]));
    }

    float bz[8];
    *(float4*)&bz[0] = *(const float4*)&bias[fg];
    *(float4*)&bz[4] = *(const float4*)&bias[fg + 4];

    float s[8], q[8];
#pragma unroll
    for (int j = 0; j < 8; j++) { s[j] = 0.f; q[j] = 0.f; }

#pragma unroll
    for (int i = 0; i < 4; i++) {
        int n = base + ng + i;
        if (n < NN) {
            float o[8];
#pragma unroll
            for (int j = 0; j < 8; j++) o[j] = acc[i][j] + bz[j];
            *(float4*)&Out[(size_t)n * 64 + fg]     = make_float4(o[0], o[1], o[2], o[3]);
            *(float4*)&Out[(size_t)n * 64 + fg + 4] = make_float4(o[4], o[5], o[6], o[7]);
            if (STATS) {
#pragma unroll
                for (int j = 0; j < 8; j++) { s[j] += o[j]; q[j] += o[j] * o[j]; }
            }
        }
    }
    if (STATS) {
#pragma unroll
        for (int j = 0; j < 8; j++) {
            atomicAdd(&sSum[fg + j], s[j]);
            atomicAdd(&sSq[fg + j], q[j]);
        }
        __syncthreads();
        if (tid < 64) {
            atomicAdd(&stats[tid], sSum[tid]);
            atomicAdd(&stats[64 + tid], sSq[tid]);
        }
    }
}

// -------------------- batchnorm finalize --------------------
__global__ void bn_finalize(const float* __restrict__ stats, const float* __restrict__ g,
                            const float* __restrict__ be, float* __restrict__ ss) {
    int f = threadIdx.x;
    const float inv = 1.f / (float)NN;
    float m = stats[f] * inv;
    float var = stats[64 + f] * inv - m * m;
    float sc = g[f] * rsqrtf(var + 1e-5f);
    ss[f] = sc;
    ss[64 + f] = fmaf(-m, sc, be[f]);
}

// -------------------- pooling + head --------------------
__global__ void pool_scatter(const float* __restrict__ h, const int* __restrict__ batch,
                             float* pool, float* cnt) {
    int i = blockIdx.x * blockDim.x + threadIdx.x;
    if (i >= NN * 16) return;
    int n = i >> 4, v = i & 15;
    int b = batch[n];
    float4 hv = ((const float4*)h)[i];
    red_add_f4(&pool[(size_t)b * 64 + v * 4], hv.x, hv.y, hv.z, hv.w);
    if (v == 0) atomicAdd(&cnt[b], 1.f);
}

__global__ void head_kernel(const float* __restrict__ pool, const float* __restrict__ cnt,
                            const float* __restrict__ Wl1, const float* __restrict__ bl1,
                            const float* __restrict__ Wl2, const float* __restrict__ bl2,
                            float* __restrict__ out) {
    __shared__ float sp[64], sz[64];
    int g = blockIdx.x, t = threadIdx.x;
    float c = fmaxf(cnt[g], 1.f);
    sp[t] = pool[g * 64 + t] / c;
    __syncthreads();
    float z = bl1[t];
#pragma unroll 8
    for (int k = 0; k < 64; k++) z = fmaf(sp[k], Wl1[k * 64 + t], z);
    sz[t] = fmaxf(z, 0.f);
    __syncthreads();
    if (t < 6) {
        float o = bl2[t];
#pragma unroll 8
        for (int k = 0; k < 64; k++) o = fmaf(sz[k], Wl2[k * 6 + t], o);
        out[g * 6 + t] = o;
    }
}

// -------------------- launch --------------------
extern "C" void kernel_launch(void* const* d_in, const int* in_sizes, int n_in,
                              void* d_out, int out_size) {
    const float* x     = (const float*)d_in[0];
    const int*   ei    = (const int*)d_in[1];
    const float* ew    = (const float*)d_in[2];
    const int*   batch = (const int*)d_in[3];
    const float *Wrel0 = (const float*)d_in[4],  *Wroot0 = (const float*)d_in[5],  *b0 = (const float*)d_in[6];
    const float *Wrel1 = (const float*)d_in[7],  *Wroot1 = (const float*)d_in[8],  *b1 = (const float*)d_in[9];
    const float *Wrel2 = (const float*)d_in[10], *Wroot2 = (const float*)d_in[11], *b2 = (const float*)d_in[12];
    const float *g0 = (const float*)d_in[13], *be0 = (const float*)d_in[14];
    const float *g1 = (const float*)d_in[15], *be1 = (const float*)d_in[16];
    const float *Wl1 = (const float*)d_in[17], *bl1 = (const float*)d_in[18];
    const float *Wl2 = (const float*)d_in[19], *bl2 = (const float*)d_in[20];
    float* out = (float*)d_out;

    const int* src = ei;
    const int* dst = ei + EE;

    float *pA, *pB, *pC, *pX, *pStats, *pSS, *pPool, *pCnt;
    int *pOff, *pCur, *pBsum;
    int2* pEpack;
    cudaGetSymbolAddress((void**)&pA, g_A);
    cudaGetSymbolAddress((void**)&pB, g_B);
    cudaGetSymbolAddress((void**)&pC, g_C);
    cudaGetSymbolAddress((void**)&pX, g_xpad);
    cudaGetSymbolAddress((void**)&pStats, g_stats);
    cudaGetSymbolAddress((void**)&pSS, g_ss);
    cudaGetSymbolAddress((void**)&pPool, g_pool);
    cudaGetSymbolAddress((void**)&pCnt, g_cnt);
    cudaGetSymbolAddress((void**)&pOff, g_off);
    cudaGetSymbolAddress((void**)&pCur, g_cur);
    cudaGetSymbolAddress((void**)&pBsum, g_bsum);
    cudaGetSymbolAddress((void**)&pEpack, g_epack);

    const int smem64 = (64 * 65 * 2 + 64 * 64 * 2 + 128) * (int)sizeof(float);  // 66560 B
    const int smem9  = (64 * 17 * 2 + 9 * 64 * 2 + 128) * (int)sizeof(float);
    cudaFuncSetAttribute((const void*)node_update<64, 64, true, true>,
                         cudaFuncAttributeMaxDynamicSharedMemorySize, smem64);
    cudaFuncSetAttribute((const void*)node_update<64, 64, false, true>,
                         cudaFuncAttributeMaxDynamicSharedMemorySize, smem64);

    const int NB = (NN + 63) / 64;
    const int SCAN_BLOCKS = (NN + 1 + 1023) / 1024;  // 98

    // ---- prep + CSR build ----
    make_xpad<<<(NN * 16 + 255) / 256, 256>>>(x, pX);
    cudaMemsetAsync(pOff, 0, (NN + 1) * sizeof(int));
    hist_kernel<<<(EE + 511) / 512, 512>>>(dst, pOff);
    scan1<<<SCAN_BLOCKS, 1024>>>(pOff, pBsum);
    scan2<<<1, 128>>>(pBsum, SCAN_BLOCKS);
    scan3<<<SCAN_BLOCKS, 1024>>>(pOff, pBsum, pCur);
    place_kernel<<<(EE + 511) / 512, 512>>>(src, dst, ew, pCur, pEpack);

    // ---- layer 0 (K=9 in padded-16 space) ----
    agg_csr<4, false><<<(NN + 63) / 64, 256>>>(pX, pOff, pEpack, nullptr, pA);
    cudaMemsetAsync(pStats, 0, 128 * sizeof(float));
    node_update<9, 16, true, false><<<NB, 128, smem9>>>(pA, pX, Wrel0, Wroot0, b0, nullptr, pB, pStats);
    bn_finalize<<<1, 64>>>(pStats, g0, be0, pSS);

    // ---- layer 1 (BN0+ReLU fused into gather and Xin) ----
    agg_csr<16, true><<<(NN + 15) / 16, 256>>>(pB, pOff, pEpack, pSS, pA);
    cudaMemsetAsync(pStats, 0, 128 * sizeof(float));
    node_update<64, 64, true, true><<<NB, 128, smem64>>>(pA, pB, Wrel1, Wroot1, b1, pSS, pC, pStats);
    bn_finalize<<<1, 64>>>(pStats, g1, be1, pSS);

    // ---- layer 2 (BN1+ReLU fused; no BN on output) ----
    agg_csr<16, true><<<(NN + 15) / 16, 256>>>(pC, pOff, pEpack, pSS, pA);
    node_update<64, 64, false, true><<<NB, 128, smem64>>>(pA, pC, Wrel2, Wroot2, b2, pSS, pB, nullptr);

    // ---- pool + head ----
    cudaMemsetAsync(pPool, 0, GG * 64 * sizeof(float));
    cudaMemsetAsync(pCnt, 0, GG * sizeof(float));
    pool_scatter<<<(NN * 16 + 255) / 256, 256>>>(pB, batch, pPool, pCnt);
    head_kernel<<<GG, 64>>>(pPool, pCnt, Wl1, bl1, Wl2, bl2, out);
}

// round 4
// speedup vs baseline: 1.6045x; 1.2933x over previous
#include <cuda_runtime.h>

#define NN 100000
#define EE 1600000
#define GG 1024

typedef unsigned long long ull;

// -------------------- device scratch --------------------
__device__ float g_A[(size_t)NN * 64];     // aggregation output
__device__ float g_B[(size_t)NN * 64];     // raw layer outputs
__device__ float g_C[(size_t)NN * 64];     // activated layer outputs
__device__ float g_xpad[(size_t)NN * 16];
__device__ int   g_off[NN + 1];            // CSR row pointers (by dst)
__device__ int   g_cur[NN];
__device__ int   g_bsum[128];
__device__ int2  g_epack[EE];              // (src, weight-bits) grouped by dst
__device__ int   g_goff[GG + 1];           // graph node offsets (batch sorted)
__device__ float g_stats[128];
__device__ float g_ss[128];                // BN scale[64] + shift[64]

__device__ __forceinline__ void fma2(ull& d, ull a, ull b) {
    asm("fma.rn.f32x2 %0, %1, %2, %0;" : "+l"(d) : "l"(a), "l"(b));
}
__device__ __forceinline__ float2 unpack2(ull v) {
    float2 r; asm("mov.b64 {%0,%1}, %2;" : "=f"(r.x), "=f"(r.y) : "l"(v)); return r;
}
__device__ __forceinline__ ull pack2(float lo, float hi) {
    ull r; asm("mov.b64 %0, {%1,%2};" : "=l"(r) : "f"(lo), "f"(hi)); return r;
}

// -------------------- prep --------------------
__global__ void make_xpad(const float* __restrict__ x, float* __restrict__ xp) {
    int i = blockIdx.x * blockDim.x + threadIdx.x;
    if (i < NN * 16) { int n = i >> 4, c = i & 15; xp[i] = (c < 9) ? x[n * 9 + c] : 0.f; }
}

// -------------------- CSR build --------------------
__global__ void hist_kernel(const int* __restrict__ dst, int* __restrict__ off) {
    int e = blockIdx.x * blockDim.x + threadIdx.x;
    if (e < EE) atomicAdd(&off[dst[e] + 1], 1);
}

__global__ void scan1(int* __restrict__ off, int* __restrict__ bsum) {
    __shared__ int ws[32];
    int g = blockIdx.x * 1024 + threadIdx.x;
    int v = (g <= NN) ? off[g] : 0;
    int lane = threadIdx.x & 31;
#pragma unroll
    for (int d = 1; d < 32; d <<= 1) { int t = __shfl_up_sync(~0u, v, d); if (lane >= d) v += t; }
    if (lane == 31) ws[threadIdx.x >> 5] = v;
    __syncthreads();
    if (threadIdx.x < 32) {
        int t = ws[threadIdx.x];
#pragma unroll
        for (int d = 1; d < 32; d <<= 1) { int u = __shfl_up_sync(~0u, t, d); if (threadIdx.x >= d) t += u; }
        ws[threadIdx.x] = t;
    }
    __syncthreads();
    if (threadIdx.x >= 32) v += ws[(threadIdx.x >> 5) - 1];
    if (g <= NN) off[g] = v;
    if (threadIdx.x == 1023) bsum[blockIdx.x] = v;
}

__global__ void scan2(int* __restrict__ bsum, int nb) {
    __shared__ int ws[4];
    int t = threadIdx.x;
    int v = (t < nb) ? bsum[t] : 0;
    int lane = t & 31, w = t >> 5;
#pragma unroll
    for (int d = 1; d < 32; d <<= 1) { int u = __shfl_up_sync(~0u, v, d); if (lane >= d) v += u; }
    if (lane == 31) ws[w] = v;
    __syncthreads();
    if (t == 0) { int r = 0; for (int i = 0; i < 4; i++) { r += ws[i]; ws[i] = r; } }
    __syncthreads();
    if (w > 0) v += ws[w - 1];
    if (t < nb) bsum[t] = v;
}

__global__ void scan3(int* __restrict__ off, const int* __restrict__ bsum, int* __restrict__ cur) {
    int g = blockIdx.x * 1024 + threadIdx.x;
    if (g > NN) return;
    int add = (blockIdx.x == 0) ? 0 : bsum[blockIdx.x - 1];
    int v = off[g] + add;
    if (blockIdx.x > 0) off[g] = v;
    if (g < NN) cur[g] = v;
}

__global__ void place_kernel(const int* __restrict__ src, const int* __restrict__ dst,
                             const float* __restrict__ ew, int* __restrict__ cur,
                             int2* __restrict__ epack) {
    int e = blockIdx.x * blockDim.x + threadIdx.x;
    if (e >= EE) return;
    int p = atomicAdd(&cur[dst[e]], 1);
    epack[p] = make_int2(src[e], __float_as_int(ew[e]));
}

// graph boundaries from sorted batch
__global__ void graph_bounds(const int* __restrict__ batch, int* __restrict__ goff) {
    int i = blockIdx.x * blockDim.x + threadIdx.x;
    if (i >= NN) return;
    int bi = batch[i];
    if (i == 0) { for (int g = 0; g <= bi; g++) goff[g] = 0; }
    else {
        int bp = batch[i - 1];
        for (int g = bp + 1; g <= bi; g++) goff[g] = i;
    }
    if (i == NN - 1) { for (int g = bi + 1; g <= GG; g++) goff[g] = NN; }
}

// -------------------- CSR aggregation (gather, register accumulate, one store) ----
template <int LPN>
__global__ void __launch_bounds__(256) agg_csr(
    const float* __restrict__ h, const int* __restrict__ rowptr,
    const int2* __restrict__ epack, float* __restrict__ agg) {
    constexpr int NPB = 256 / LPN;
    int node = blockIdx.x * NPB + threadIdx.x / LPN;
    int lane = threadIdx.x % LPN;
    if (node >= NN) return;
    int beg = rowptr[node], end = rowptr[node + 1];
    float4 acc = make_float4(0.f, 0.f, 0.f, 0.f);
    for (int i = beg; i < end; ++i) {
        int2 ep = epack[i];
        float w = __int_as_float(ep.y);
        float4 v = ((const float4*)h)[(size_t)ep.x * LPN + lane];
        acc.x = fmaf(v.x, w, acc.x);
        acc.y = fmaf(v.y, w, acc.y);
        acc.z = fmaf(v.z, w, acc.z);
        acc.w = fmaf(v.w, w, acc.w);
    }
    ((float4*)agg)[(size_t)node * LPN + lane] = acc;
}

// -------------------- layer-0 node update (K=9, scalar) --------------------
__global__ void __launch_bounds__(128) node_update9(
    const float* __restrict__ Ag, const float* __restrict__ Xin,
    const float* __restrict__ Wrel, const float* __restrict__ Wroot,
    const float* __restrict__ bias, float* __restrict__ Out, float* stats) {
    constexpr int K = 9, PAD = 17, C4 = 4;
    extern __shared__ float sm[];
    float* sA   = sm;                // 64*PAD
    float* sX   = sA + 64 * PAD;
    float* sWr  = sX + 64 * PAD;     // K*64
    float* sWo  = sWr + K * 64;
    float* sSum = sWo + K * 64;
    float* sSq  = sSum + 64;

    const int tid = threadIdx.x;
    const int base = blockIdx.x * 64;

    for (int i = tid; i < K * 16; i += 128) {
        ((float4*)sWr)[i] = ((const float4*)Wrel)[i];
        ((float4*)sWo)[i] = ((const float4*)Wroot)[i];
    }
    for (int i = tid; i < 64 * C4; i += 128) {
        int r = i / C4, c = i - r * C4;
        int n = base + r;
        float4 va = make_float4(0.f, 0.f, 0.f, 0.f), vx = va;
        if (n < NN) {
            va = *(const float4*)&Ag[(size_t)n * 16 + c * 4];
            vx = *(const float4*)&Xin[(size_t)n * 16 + c * 4];
        }
        int o = r * PAD + c * 4;
        sA[o] = va.x; sA[o + 1] = va.y; sA[o + 2] = va.z; sA[o + 3] = va.w;
        sX[o] = vx.x; sX[o + 1] = vx.y; sX[o + 2] = vx.z; sX[o + 3] = vx.w;
    }
    if (tid < 64) { sSum[tid] = 0.f; sSq[tid] = 0.f; }
    __syncthreads();

    const int fg = (tid & 7) * 8;
    const int ng = (tid >> 3) * 4;

    float acc[4][8];
#pragma unroll
    for (int i = 0; i < 4; i++)
#pragma unroll
        for (int j = 0; j < 8; j++) acc[i][j] = 0.f;

#pragma unroll
    for (int k = 0; k < K; ++k) {
        float a[4], xv[4];
#pragma unroll
        for (int i = 0; i < 4; i++) {
            a[i]  = sA[(ng + i) * PAD + k];
            xv[i] = sX[(ng + i) * PAD + k];
        }
        float wr[8], wo[8];
        *(float4*)&wr[0] = *(const float4*)&sWr[k * 64 + fg];
        *(float4*)&wr[4] = *(const float4*)&sWr[k * 64 + fg + 4];
        *(float4*)&wo[0] = *(const float4*)&sWo[k * 64 + fg];
        *(float4*)&wo[4] = *(const float4*)&sWo[k * 64 + fg + 4];
#pragma unroll
        for (int i = 0; i < 4; i++)
#pragma unroll
            for (int j = 0; j < 8; j++)
                acc[i][j] = fmaf(xv[i], wo[j], fmaf(a[i], wr[j], acc[i][j]));
    }

    float bz[8];
    *(float4*)&bz[0] = *(const float4*)&bias[fg];
    *(float4*)&bz[4] = *(const float4*)&bias[fg + 4];

    float s[8], q[8];
#pragma unroll
    for (int j = 0; j < 8; j++) { s[j] = 0.f; q[j] = 0.f; }

#pragma unroll
    for (int i = 0; i < 4; i++) {
        int n = base + ng + i;
        if (n < NN) {
            float o[8];
#pragma unroll
            for (int j = 0; j < 8; j++) o[j] = acc[i][j] + bz[j];
            *(float4*)&Out[(size_t)n * 64 + fg]     = make_float4(o[0], o[1], o[2], o[3]);
            *(float4*)&Out[(size_t)n * 64 + fg + 4] = make_float4(o[4], o[5], o[6], o[7]);
#pragma unroll
            for (int j = 0; j < 8; j++) { s[j] += o[j]; q[j] += o[j] * o[j]; }
        }
    }
#pragma unroll
    for (int j = 0; j < 8; j++) {
        atomicAdd(&sSum[fg + j], s[j]);
        atomicAdd(&sSq[fg + j], q[j]);
    }
    __syncthreads();
    if (tid < 64) {
        atomicAdd(&stats[tid], sSum[tid]);
        atomicAdd(&stats[64 + tid], sSq[tid]);
    }
}

// -------------------- f32x2 node update (K=64) --------------------
// Accumulators pack (k-even, k-odd) partial sums; merged at the end.
// Thread owns features f = 2*(tid&7) + 16c + e (c=0..3, e=0..1): weight LDS.128
// addresses are conflict-free across the warp.
template <bool STATS>
__global__ void __launch_bounds__(128) node_update64(
    const float* __restrict__ Ag, const float* __restrict__ Xin,
    const float* __restrict__ Wrel, const float* __restrict__ Wroot,
    const float* __restrict__ bias, float* __restrict__ Out, float* stats) {
    constexpr int PAD = 66;
    extern __shared__ float sm[];
    float* sA   = sm;                 // 64*66
    float* sX   = sA + 64 * PAD;      // 64*66
    ull*   sWr  = (ull*)(sX + 64 * PAD);   // 32 k2 x 64 f
    ull*   sWo  = sWr + 32 * 64;
    float* sSum = (float*)(sWo + 32 * 64);
    float* sSq  = sSum + 64;

    const int tid = threadIdx.x;
    const int base = blockIdx.x * 64;

    // stage packed weights: sW[k2*64 + f] = (W[2k2][f], W[2k2+1][f])
    for (int idx = tid; idx < 32 * 16; idx += 128) {
        int k2 = idx >> 4, c4 = idx & 15;
        float4 r0 = ((const float4*)Wrel)[(2 * k2) * 16 + c4];
        float4 r1 = ((const float4*)Wrel)[(2 * k2 + 1) * 16 + c4];
        ull* p = &sWr[k2 * 64 + c4 * 4];
        p[0] = pack2(r0.x, r1.x); p[1] = pack2(r0.y, r1.y);
        p[2] = pack2(r0.z, r1.z); p[3] = pack2(r0.w, r1.w);
        r0 = ((const float4*)Wroot)[(2 * k2) * 16 + c4];
        r1 = ((const float4*)Wroot)[(2 * k2 + 1) * 16 + c4];
        p = &sWo[k2 * 64 + c4 * 4];
        p[0] = pack2(r0.x, r1.x); p[1] = pack2(r0.y, r1.y);
        p[2] = pack2(r0.z, r1.z); p[3] = pack2(r0.w, r1.w);
    }
    // stage node rows
    for (int i = tid; i < 64 * 16; i += 128) {
        int r = i >> 4, c = i & 15;
        int n = base + r;
        float4 va = make_float4(0.f, 0.f, 0.f, 0.f), vx = va;
        if (n < NN) {
            va = *(const float4*)&Ag[(size_t)n * 64 + c * 4];
            vx = *(const float4*)&Xin[(size_t)n * 64 + c * 4];
        }
        int o = r * PAD + c * 4;
        sA[o] = va.x; sA[o + 1] = va.y; sA[o + 2] = va.z; sA[o + 3] = va.w;
        sX[o] = vx.x; sX[o + 1] = vx.y; sX[o + 2] = vx.z; sX[o + 3] = vx.w;
    }
    if (STATS && tid < 64) { sSum[tid] = 0.f; sSq[tid] = 0.f; }
    __syncthreads();

    const int f0 = (tid & 7) * 2;
    const int ng = (tid >> 3) * 4;

    ull acc2[4][8];
#pragma unroll
    for (int i = 0; i < 4; i++)
#pragma unroll
        for (int j = 0; j < 8; j++) acc2[i][j] = 0ull;

#pragma unroll 2
    for (int k2 = 0; k2 < 32; ++k2) {
        ull av[4], xv[4];
#pragma unroll
        for (int i = 0; i < 4; i++) {
            av[i] = *(const ull*)&sA[(ng + i) * PAD + 2 * k2];
            xv[i] = *(const ull*)&sX[(ng + i) * PAD + 2 * k2];
        }
#pragma unroll
        for (int c = 0; c < 4; c++) {
            ulonglong2 wr = *(const ulonglong2*)&sWr[k2 * 64 + f0 + 16 * c];
            ulonglong2 wo = *(const ulonglong2*)&sWo[k2 * 64 + f0 + 16 * c];
#pragma unroll
            for (int i = 0; i < 4; i++) {
                fma2(acc2[i][2 * c],     av[i], wr.x);
                fma2(acc2[i][2 * c + 1], av[i], wr.y);
                fma2(acc2[i][2 * c],     xv[i], wo.x);
                fma2(acc2[i][2 * c + 1], xv[i], wo.y);
            }
        }
    }

    float bz[8];
#pragma unroll
    for (int c = 0; c < 4; c++) {
        float2 b2 = *(const float2*)&bias[f0 + 16 * c];
        bz[2 * c] = b2.x; bz[2 * c + 1] = b2.y;
    }

    float s[8], q[8];
#pragma unroll
    for (int j = 0; j < 8; j++) { s[j] = 0.f; q[j] = 0.f; }

#pragma unroll
    for (int i = 0; i < 4; i++) {
        int n = base + ng + i;
        if (n < NN) {
#pragma unroll
            for (int c = 0; c < 4; c++) {
                float2 e0 = unpack2(acc2[i][2 * c]);
                float2 e1 = unpack2(acc2[i][2 * c + 1]);
                float o0 = e0.x + e0.y + bz[2 * c];
                float o1 = e1.x + e1.y + bz[2 * c + 1];
                *(float2*)&Out[(size_t)n * 64 + f0 + 16 * c] = make_float2(o0, o1);
                if (STATS) {
                    s[2 * c] += o0; q[2 * c] += o0 * o0;
                    s[2 * c + 1] += o1; q[2 * c + 1] += o1 * o1;
                }
            }
        }
    }
    if (STATS) {
#pragma unroll
        for (int c = 0; c < 4; c++) {
            atomicAdd(&sSum[f0 + 16 * c],     s[2 * c]);
            atomicAdd(&sSum[f0 + 16 * c + 1], s[2 * c + 1]);
            atomicAdd(&sSq[f0 + 16 * c],      q[2 * c]);
            atomicAdd(&sSq[f0 + 16 * c + 1],  q[2 * c + 1]);
        }
        __syncthreads();
        if (tid < 64) {
            atomicAdd(&stats[tid], sSum[tid]);
            atomicAdd(&stats[64 + tid], sSq[tid]);
        }
    }
}

// -------------------- batchnorm --------------------
__global__ void bn_finalize(const float* __restrict__ stats, const float* __restrict__ g,
                            const float* __restrict__ be, float* __restrict__ ss) {
    int f = threadIdx.x;
    const float inv = 1.f / (float)NN;
    float m = stats[f] * inv;
    float var = stats[64 + f] * inv - m * m;
    float sc = g[f] * rsqrtf(var + 1e-5f);
    ss[f] = sc;
    ss[64 + f] = fmaf(-m, sc, be[f]);
}

__global__ void bn_act(const float* __restrict__ in, const float* __restrict__ ss,
                       float* __restrict__ outb) {
    int i = blockIdx.x * blockDim.x + threadIdx.x;
    if (i >= NN * 16) return;
    int v = i & 15;
    float4 h = ((const float4*)in)[i];
    float4 sc = ((const float4*)ss)[v];
    float4 sh = ((const float4*)ss)[16 + v];
    h.x = fmaxf(fmaf(h.x, sc.x, sh.x), 0.f);
    h.y = fmaxf(fmaf(h.y, sc.y, sh.y), 0.f);
    h.z = fmaxf(fmaf(h.z, sc.z, sh.z), 0.f);
    h.w = fmaxf(fmaf(h.w, sc.w, sh.w), 0.f);
    ((float4*)outb)[i] = h;
}

// -------------------- fused pool + head (batch sorted -> contiguous segments) ----
__global__ void pool_head(const float* __restrict__ h, const int* __restrict__ goff,
                          const float* __restrict__ Wl1, const float* __restrict__ bl1,
                          const float* __restrict__ Wl2, const float* __restrict__ bl2,
                          float* __restrict__ out) {
    __shared__ float sz[64];
    int g = blockIdx.x, t = threadIdx.x;
    int beg = goff[g], end = goff[g + 1];
    float s = 0.f;
    for (int n = beg; n < end; ++n) s += h[(size_t)n * 64 + t];
    float c = fmaxf((float)(end - beg), 1.f);
    __shared__ float sp[64];
    sp[t] = s / c;
    __syncthreads();
    float z = bl1[t];
#pragma unroll 8
    for (int k = 0; k < 64; k++) z = fmaf(sp[k], Wl1[k * 64 + t], z);
    sz[t] = fmaxf(z, 0.f);
    __syncthreads();
    if (t < 6) {
        float o = bl2[t];
#pragma unroll 8
        for (int k = 0; k < 64; k++) o = fmaf(sz[k], Wl2[k * 6 + t], o);
        out[g * 6 + t] = o;
    }
}

// -------------------- launch --------------------
extern "C" void kernel_launch(void* const* d_in, const int* in_sizes, int n_in,
                              void* d_out, int out_size) {
    const float* x     = (const float*)d_in[0];
    const int*   ei    = (const int*)d_in[1];
    const float* ew    = (const float*)d_in[2];
    const int*   batch = (const int*)d_in[3];
    const float *Wrel0 = (const float*)d_in[4],  *Wroot0 = (const float*)d_in[5],  *b0 = (const float*)d_in[6];
    const float *Wrel1 = (const float*)d_in[7],  *Wroot1 = (const float*)d_in[8],  *b1 = (const float*)d_in[9];
    const float *Wrel2 = (const float*)d_in[10], *Wroot2 = (const float*)d_in[11], *b2 = (const float*)d_in[12];
    const float *g0 = (const float*)d_in[13], *be0 = (const float*)d_in[14];
    const float *g1 = (const float*)d_in[15], *be1 = (const float*)d_in[16];
    const float *Wl1 = (const float*)d_in[17], *bl1 = (const float*)d_in[18];
    const float *Wl2 = (const float*)d_in[19], *bl2 = (const float*)d_in[20];
    float* out = (float*)d_out;

    const int* src = ei;
    const int* dst = ei + EE;

    float *pA, *pB, *pC, *pX, *pStats, *pSS;
    int *pOff, *pCur, *pBsum, *pGoff;
    int2* pEpack;
    cudaGetSymbolAddress((void**)&pA, g_A);
    cudaGetSymbolAddress((void**)&pB, g_B);
    cudaGetSymbolAddress((void**)&pC, g_C);
    cudaGetSymbolAddress((void**)&pX, g_xpad);
    cudaGetSymbolAddress((void**)&pStats, g_stats);
    cudaGetSymbolAddress((void**)&pSS, g_ss);
    cudaGetSymbolAddress((void**)&pOff, g_off);
    cudaGetSymbolAddress((void**)&pCur, g_cur);
    cudaGetSymbolAddress((void**)&pBsum, g_bsum);
    cudaGetSymbolAddress((void**)&pGoff, g_goff);
    cudaGetSymbolAddress((void**)&pEpack, g_epack);

    const int smem64 = 64 * 66 * 4 * 2 + 32 * 64 * 8 * 2 + 128 * 4;  // 67072 B
    const int smem9  = (64 * 17 * 2 + 9 * 64 * 2 + 128) * (int)sizeof(float);
    cudaFuncSetAttribute((const void*)node_update64<true>,
                         cudaFuncAttributeMaxDynamicSharedMemorySize, smem64);
    cudaFuncSetAttribute((const void*)node_update64<false>,
                         cudaFuncAttributeMaxDynamicSharedMemorySize, smem64);

    const int NB = (NN + 63) / 64;
    const int SCAN_BLOCKS = (NN + 1 + 1023) / 1024;

    // ---- CSR build + prep ----
    cudaMemsetAsync(pOff, 0, (NN + 1) * sizeof(int));
    hist_kernel<<<(EE + 511) / 512, 512>>>(dst, pOff);
    scan1<<<SCAN_BLOCKS, 1024>>>(pOff, pBsum);
    scan2<<<1, 128>>>(pBsum, SCAN_BLOCKS);
    scan3<<<SCAN_BLOCKS, 1024>>>(pOff, pBsum, pCur);
    place_kernel<<<(EE + 511) / 512, 512>>>(src, dst, ew, pCur, pEpack);
    make_xpad<<<(NN * 16 + 255) / 256, 256>>>(x, pX);
    graph_bounds<<<(NN + 255) / 256, 256>>>(batch, pGoff);

    // ---- layer 0 (K=9 in padded-16 space) ----
    agg_csr<4><<<(NN + 63) / 64, 256>>>(pX, pOff, pEpack, pA);
    cudaMemsetAsync(pStats, 0, 128 * sizeof(float));
    node_update9<<<NB, 128, smem9>>>(pA, pX, Wrel0, Wroot0, b0, pB, pStats);
    bn_finalize<<<1, 64>>>(pStats, g0, be0, pSS);
    bn_act<<<(NN * 16 + 255) / 256, 256>>>(pB, pSS, pC);

    // ---- layer 1 ----
    agg_csr<16><<<(NN + 15) / 16, 256>>>(pC, pOff, pEpack, pA);
    cudaMemsetAsync(pStats, 0, 128 * sizeof(float));
    node_update64<true><<<NB, 128, smem64>>>(pA, pC, Wrel1, Wroot1, b1, pB, pStats);
    bn_finalize<<<1, 64>>>(pStats, g1, be1, pSS);
    bn_act<<<(NN * 16 + 255) / 256, 256>>>(pB, pSS, pC);

    // ---- layer 2 (no BN) ----
    agg_csr<16><<<(NN + 15) / 16, 256>>>(pC, pOff, pEpack, pA);
    node_update64<false><<<NB, 128, smem64>>>(pA, pC, Wrel2, Wroot2, b2, pB, nullptr);

    // ---- fused pool + head ----
    pool_head<<<GG, 64>>>(pB, pGoff, Wl1, bl1, Wl2, bl2, out);
}

// round 5
// speedup vs baseline: 1.7745x; 1.1060x over previous
#include <cuda_runtime.h>
#include <cuda_fp16.h>

#define NN 100000
#define EE 1600000
#define GG 1024

typedef unsigned long long ull;

// -------------------- device scratch --------------------
__device__ float g_A[(size_t)NN * 64];     // aggregation output (fp32)
__device__ float g_B[(size_t)NN * 64];     // raw layer outputs (fp32)
__device__ uint4 g_H[(size_t)NN * 8];      // activated features as fp16 (64 halves/node)
__device__ float g_xpad[(size_t)NN * 16];
__device__ int   g_off[NN + 1];            // CSR row pointers (by dst)
__device__ int   g_cur[NN];
__device__ int   g_bsum[128];
__device__ int2  g_epack[EE];              // (src, weight-bits) grouped by dst
__device__ int   g_goff[GG + 1];
__device__ float g_stats[128];

__device__ __forceinline__ void fma2(ull& d, ull a, ull b) {
    asm("fma.rn.f32x2 %0, %1, %2, %0;" : "+l"(d) : "l"(a), "l"(b));
}
__device__ __forceinline__ float2 unpack2(ull v) {
    float2 r; asm("mov.b64 {%0,%1}, %2;" : "=f"(r.x), "=f"(r.y) : "l"(v)); return r;
}
__device__ __forceinline__ ull pack2(float lo, float hi) {
    ull r; asm("mov.b64 %0, {%1,%2};" : "=l"(r) : "f"(lo), "f"(hi)); return r;
}

// -------------------- fused prep: hist + xpad + graph bounds --------------------
__global__ void prep(const float* __restrict__ x, float* __restrict__ xp,
                     const int* __restrict__ dst, int* __restrict__ off,
                     const int* __restrict__ batch, int* __restrict__ goff) {
    int i = blockIdx.x * blockDim.x + threadIdx.x;
    if (i < EE) atomicAdd(&off[dst[i] + 1], 1);
    if (i < NN * 16) { int n = i >> 4, c = i & 15; xp[i] = (c < 9) ? x[n * 9 + c] : 0.f; }
    if (i < NN) {
        int bi = batch[i];
        if (i == 0) { for (int g = 0; g <= bi; g++) goff[g] = 0; }
        else { int bp = batch[i - 1]; for (int g = bp + 1; g <= bi; g++) goff[g] = i; }
        if (i == NN - 1) { for (int g = bi + 1; g <= GG; g++) goff[g] = NN; }
    }
}

// -------------------- scan --------------------
__global__ void scan1(int* __restrict__ off, int* __restrict__ bsum) {
    __shared__ int ws[32];
    int g = blockIdx.x * 1024 + threadIdx.x;
    int v = (g <= NN) ? off[g] : 0;
    int lane = threadIdx.x & 31;
#pragma unroll
    for (int d = 1; d < 32; d <<= 1) { int t = __shfl_up_sync(~0u, v, d); if (lane >= d) v += t; }
    if (lane == 31) ws[threadIdx.x >> 5] = v;
    __syncthreads();
    if (threadIdx.x < 32) {
        int t = ws[threadIdx.x];
#pragma unroll
        for (int d = 1; d < 32; d <<= 1) { int u = __shfl_up_sync(~0u, t, d); if (threadIdx.x >= d) t += u; }
        ws[threadIdx.x] = t;
    }
    __syncthreads();
    if (threadIdx.x >= 32) v += ws[(threadIdx.x >> 5) - 1];
    if (g <= NN) off[g] = v;
    if (threadIdx.x == 1023) bsum[blockIdx.x] = v;
}

// fused: add prefix of bsum (computed per block) and emit cursors
__global__ void scan3f(int* __restrict__ off, const int* __restrict__ bsum, int* __restrict__ cur) {
    __shared__ int red[32];
    __shared__ int sadd;
    int t = threadIdx.x;
    int v = (t < blockIdx.x) ? bsum[t] : 0;   // blockIdx < 98 < 1024
#pragma unroll
    for (int d = 16; d; d >>= 1) v += __shfl_down_sync(~0u, v, d);
    if ((t & 31) == 0) red[t >> 5] = v;
    __syncthreads();
    if (t == 0) { int r = 0; for (int w = 0; w < 32; w++) r += red[w]; sadd = r; }
    __syncthreads();
    int g = blockIdx.x * 1024 + t;
    if (g > NN) return;
    int val = off[g] + sadd;
    off[g] = val;
    if (g < NN) cur[g] = val;
}

__global__ void place_kernel(const int* __restrict__ src, const int* __restrict__ dst,
                             const float* __restrict__ ew, int* __restrict__ cur,
                             int2* __restrict__ epack) {
    int e = blockIdx.x * blockDim.x + threadIdx.x;
    if (e >= EE) return;
    int p = atomicAdd(&cur[dst[e]], 1);
    epack[p] = make_int2(src[e], __float_as_int(ew[e]));
}

// -------------------- CSR aggregation, fp32 rows (layer 0: 16-wide padded) ------
__global__ void __launch_bounds__(256) agg_csr4(
    const float* __restrict__ h, const int* __restrict__ rowptr,
    const int2* __restrict__ epack, float* __restrict__ agg, float* __restrict__ stats) {
    if (blockIdx.x == 0 && threadIdx.x < 128) stats[threadIdx.x] = 0.f;
    int node = blockIdx.x * 64 + (threadIdx.x >> 2);
    int lane = threadIdx.x & 3;
    if (node >= NN) return;
    int beg = rowptr[node], end = rowptr[node + 1];
    float4 acc = make_float4(0.f, 0.f, 0.f, 0.f);
    for (int i = beg; i < end; ++i) {
        int2 ep = epack[i];
        float w = __int_as_float(ep.y);
        float4 v = ((const float4*)h)[(size_t)ep.x * 4 + lane];
        acc.x = fmaf(v.x, w, acc.x);
        acc.y = fmaf(v.y, w, acc.y);
        acc.z = fmaf(v.z, w, acc.z);
        acc.w = fmaf(v.w, w, acc.w);
    }
    ((float4*)agg)[(size_t)node * 4 + lane] = acc;
}

// -------------------- CSR aggregation, fp16 rows (layers 1,2) --------------------
// 8 lanes/node, each lane owns 8 features (one uint4 of halves). fp32 accumulate.
__device__ __forceinline__ void accum8(float* acc, uint4 r, float w) {
    __half2* hp = (__half2*)&r;
#pragma unroll
    for (int j = 0; j < 4; j++) {
        float2 f = __half22float2(hp[j]);
        acc[2 * j]     = fmaf(f.x, w, acc[2 * j]);
        acc[2 * j + 1] = fmaf(f.y, w, acc[2 * j + 1]);
    }
}

__global__ void __launch_bounds__(256) agg_csr_h(
    const uint4* __restrict__ h, const int* __restrict__ rowptr,
    const int2* __restrict__ epack, float* __restrict__ agg, float* stats) {
    if (stats && blockIdx.x == 0 && threadIdx.x < 128) stats[threadIdx.x] = 0.f;
    int node = blockIdx.x * 32 + (threadIdx.x >> 3);
    int lane = threadIdx.x & 7;
    if (node >= NN) return;
    int beg = rowptr[node], end = rowptr[node + 1];
    float acc[8];
#pragma unroll
    for (int j = 0; j < 8; j++) acc[j] = 0.f;
    int i = beg;
    for (; i + 1 < end; i += 2) {
        int2 e0 = epack[i], e1 = epack[i + 1];
        uint4 r0 = h[(size_t)e0.x * 8 + lane];
        uint4 r1 = h[(size_t)e1.x * 8 + lane];
        accum8(acc, r0, __int_as_float(e0.y));
        accum8(acc, r1, __int_as_float(e1.y));
    }
    if (i < end) {
        int2 e0 = epack[i];
        uint4 r0 = h[(size_t)e0.x * 8 + lane];
        accum8(acc, r0, __int_as_float(e0.y));
    }
    float* dstp = &agg[(size_t)node * 64 + lane * 8];
    *(float4*)dstp       = make_float4(acc[0], acc[1], acc[2], acc[3]);
    *(float4*)(dstp + 4) = make_float4(acc[4], acc[5], acc[6], acc[7]);
}

// -------------------- layer-0 node update (K=9, scalar) --------------------
__global__ void __launch_bounds__(128) node_update9(
    const float* __restrict__ Ag, const float* __restrict__ Xin,
    const float* __restrict__ Wrel, const float* __restrict__ Wroot,
    const float* __restrict__ bias, float* __restrict__ Out, float* stats) {
    constexpr int K = 9, PAD = 17, C4 = 4;
    extern __shared__ float sm[];
    float* sA   = sm;
    float* sX   = sA + 64 * PAD;
    float* sWr  = sX + 64 * PAD;
    float* sWo  = sWr + K * 64;
    float* sSum = sWo + K * 64;
    float* sSq  = sSum + 64;

    const int tid = threadIdx.x;
    const int base = blockIdx.x * 64;

    for (int i = tid; i < K * 16; i += 128) {
        ((float4*)sWr)[i] = ((const float4*)Wrel)[i];
        ((float4*)sWo)[i] = ((const float4*)Wroot)[i];
    }
    for (int i = tid; i < 64 * C4; i += 128) {
        int r = i / C4, c = i - r * C4;
        int n = base + r;
        float4 va = make_float4(0.f, 0.f, 0.f, 0.f), vx = va;
        if (n < NN) {
            va = *(const float4*)&Ag[(size_t)n * 16 + c * 4];
            vx = *(const float4*)&Xin[(size_t)n * 16 + c * 4];
        }
        int o = r * PAD + c * 4;
        sA[o] = va.x; sA[o + 1] = va.y; sA[o + 2] = va.z; sA[o + 3] = va.w;
        sX[o] = vx.x; sX[o + 1] = vx.y; sX[o + 2] = vx.z; sX[o + 3] = vx.w;
    }
    if (tid < 64) { sSum[tid] = 0.f; sSq[tid] = 0.f; }
    __syncthreads();

    const int fg = (tid & 7) * 8;
    const int ng = (tid >> 3) * 4;

    float acc[4][8];
#pragma unroll
    for (int i = 0; i < 4; i++)
#pragma unroll
        for (int j = 0; j < 8; j++) acc[i][j] = 0.f;

#pragma unroll
    for (int k = 0; k < K; ++k) {
        float a[4], xv[4];
#pragma unroll
        for (int i = 0; i < 4; i++) {
            a[i]  = sA[(ng + i) * PAD + k];
            xv[i] = sX[(ng + i) * PAD + k];
        }
        float wr[8], wo[8];
        *(float4*)&wr[0] = *(const float4*)&sWr[k * 64 + fg];
        *(float4*)&wr[4] = *(const float4*)&sWr[k * 64 + fg + 4];
        *(float4*)&wo[0] = *(const float4*)&sWo[k * 64 + fg];
        *(float4*)&wo[4] = *(const float4*)&sWo[k * 64 + fg + 4];
#pragma unroll
        for (int i = 0; i < 4; i++)
#pragma unroll
            for (int j = 0; j < 8; j++)
                acc[i][j] = fmaf(xv[i], wo[j], fmaf(a[i], wr[j], acc[i][j]));
    }

    float bz[8];
    *(float4*)&bz[0] = *(const float4*)&bias[fg];
    *(float4*)&bz[4] = *(const float4*)&bias[fg + 4];

    float s[8], q[8];
#pragma unroll
    for (int j = 0; j < 8; j++) { s[j] = 0.f; q[j] = 0.f; }

#pragma unroll
    for (int i = 0; i < 4; i++) {
        int n = base + ng + i;
        if (n < NN) {
            float o[8];
#pragma unroll
            for (int j = 0; j < 8; j++) o[j] = acc[i][j] + bz[j];
            *(float4*)&Out[(size_t)n * 64 + fg]     = make_float4(o[0], o[1], o[2], o[3]);
            *(float4*)&Out[(size_t)n * 64 + fg + 4] = make_float4(o[4], o[5], o[6], o[7]);
#pragma unroll
            for (int j = 0; j < 8; j++) { s[j] += o[j]; q[j] += o[j] * o[j]; }
        }
    }
#pragma unroll
    for (int j = 0; j < 8; j++) {
        atomicAdd(&sSum[fg + j], s[j]);
        atomicAdd(&sSq[fg + j], q[j]);
    }
    __syncthreads();
    if (tid < 64) {
        atomicAdd(&stats[tid], sSum[tid]);
        atomicAdd(&stats[64 + tid], sSq[tid]);
    }
}

// -------------------- f32x2 node update (K=64), fp16 Xin --------------------
template <bool STATS>
__global__ void __launch_bounds__(128) node_update64(
    const float* __restrict__ Ag, const uint4* __restrict__ Xh,
    const float* __restrict__ Wrel, const float* __restrict__ Wroot,
    const float* __restrict__ bias, float* __restrict__ Out, float* stats) {
    constexpr int PAD = 66;
    extern __shared__ float sm[];
    float* sA   = sm;
    float* sX   = sA + 64 * PAD;
    ull*   sWr  = (ull*)(sX + 64 * PAD);
    ull*   sWo  = sWr + 32 * 64;
    float* sSum = (float*)(sWo + 32 * 64);
    float* sSq  = sSum + 64;

    const int tid = threadIdx.x;
    const int base = blockIdx.x * 64;

    for (int idx = tid; idx < 32 * 16; idx += 128) {
        int k2 = idx >> 4, c4 = idx & 15;
        float4 r0 = ((const float4*)Wrel)[(2 * k2) * 16 + c4];
        float4 r1 = ((const float4*)Wrel)[(2 * k2 + 1) * 16 + c4];
        ull* p = &sWr[k2 * 64 + c4 * 4];
        p[0] = pack2(r0.x, r1.x); p[1] = pack2(r0.y, r1.y);
        p[2] = pack2(r0.z, r1.z); p[3] = pack2(r0.w, r1.w);
        r0 = ((const float4*)Wroot)[(2 * k2) * 16 + c4];
        r1 = ((const float4*)Wroot)[(2 * k2 + 1) * 16 + c4];
        p = &sWo[k2 * 64 + c4 * 4];
        p[0] = pack2(r0.x, r1.x); p[1] = pack2(r0.y, r1.y);
        p[2] = pack2(r0.z, r1.z); p[3] = pack2(r0.w, r1.w);
    }
    // stage Ag (fp32) rows
    for (int i = tid; i < 64 * 16; i += 128) {
        int r = i >> 4, c = i & 15;
        int n = base + r;
        float4 va = make_float4(0.f, 0.f, 0.f, 0.f);
        if (n < NN) va = *(const float4*)&Ag[(size_t)n * 64 + c * 4];
        int o = r * PAD + c * 4;
        sA[o] = va.x; sA[o + 1] = va.y; sA[o + 2] = va.z; sA[o + 3] = va.w;
    }
    // stage Xin (fp16) rows, convert to fp32
    for (int i = tid; i < 64 * 8; i += 128) {
        int r = i >> 3, c = i & 7;
        int n = base + r;
        uint4 v = make_uint4(0u, 0u, 0u, 0u);
        if (n < NN) v = Xh[(size_t)n * 8 + c];
        __half2* hp = (__half2*)&v;
        float* o = &sX[r * PAD + c * 8];
#pragma unroll
        for (int j = 0; j < 4; j++) {
            float2 f = __half22float2(hp[j]);
            o[2 * j] = f.x; o[2 * j + 1] = f.y;
        }
    }
    if (STATS && tid < 64) { sSum[tid] = 0.f; sSq[tid] = 0.f; }
    __syncthreads();

    const int f0 = (tid & 7) * 2;
    const int ng = (tid >> 3) * 4;

    ull acc2[4][8];
#pragma unroll
    for (int i = 0; i < 4; i++)
#pragma unroll
        for (int j = 0; j < 8; j++) acc2[i][j] = 0ull;

#pragma unroll 2
    for (int k2 = 0; k2 < 32; ++k2) {
        ull av[4], xv[4];
#pragma unroll
        for (int i = 0; i < 4; i++) {
            av[i] = *(const ull*)&sA[(ng + i) * PAD + 2 * k2];
            xv[i] = *(const ull*)&sX[(ng + i) * PAD + 2 * k2];
        }
#pragma unroll
        for (int c = 0; c < 4; c++) {
            ulonglong2 wr = *(const ulonglong2*)&sWr[k2 * 64 + f0 + 16 * c];
            ulonglong2 wo = *(const ulonglong2*)&sWo[k2 * 64 + f0 + 16 * c];
#pragma unroll
            for (int i = 0; i < 4; i++) {
                fma2(acc2[i][2 * c],     av[i], wr.x);
                fma2(acc2[i][2 * c + 1], av[i], wr.y);
                fma2(acc2[i][2 * c],     xv[i], wo.x);
                fma2(acc2[i][2 * c + 1], xv[i], wo.y);
            }
        }
    }

    float bz[8];
#pragma unroll
    for (int c = 0; c < 4; c++) {
        float2 b2 = *(const float2*)&bias[f0 + 16 * c];
        bz[2 * c] = b2.x; bz[2 * c + 1] = b2.y;
    }

    float s[8], q[8];
#pragma unroll
    for (int j = 0; j < 8; j++) { s[j] = 0.f; q[j] = 0.f; }

#pragma unroll
    for (int i = 0; i < 4; i++) {
        int n = base + ng + i;
        if (n < NN) {
#pragma unroll
            for (int c = 0; c < 4; c++) {
                float2 e0 = unpack2(acc2[i][2 * c]);
                float2 e1 = unpack2(acc2[i][2 * c + 1]);
                float o0 = e0.x + e0.y + bz[2 * c];
                float o1 = e1.x + e1.y + bz[2 * c + 1];
                *(float2*)&Out[(size_t)n * 64 + f0 + 16 * c] = make_float2(o0, o1);
                if (STATS) {
                    s[2 * c] += o0; q[2 * c] += o0 * o0;
                    s[2 * c + 1] += o1; q[2 * c + 1] += o1 * o1;
                }
            }
        }
    }
    if (STATS) {
#pragma unroll
        for (int c = 0; c < 4; c++) {
            atomicAdd(&sSum[f0 + 16 * c],     s[2 * c]);
            atomicAdd(&sSum[f0 + 16 * c + 1], s[2 * c + 1]);
            atomicAdd(&sSq[f0 + 16 * c],      q[2 * c]);
            atomicAdd(&sSq[f0 + 16 * c + 1],  q[2 * c + 1]);
        }
        __syncthreads();
        if (tid < 64) {
            atomicAdd(&stats[tid], sSum[tid]);
            atomicAdd(&stats[64 + tid], sSq[tid]);
        }
    }
}

// -------------------- BN finalize + apply + ReLU + fp16 convert (fused) --------
__global__ void __launch_bounds__(256) bn_act_h(
    const float* __restrict__ in, const float* __restrict__ stats,
    const float* __restrict__ g, const float* __restrict__ be,
    uint4* __restrict__ outh) {
    __shared__ float sc[64], sh[64];
    if (threadIdx.x < 64) {
        int f = threadIdx.x;
        const float inv = 1.f / (float)NN;
        float m = stats[f] * inv;
        float var = stats[64 + f] * inv - m * m;
        float s = g[f] * rsqrtf(var + 1e-5f);
        sc[f] = s;
        sh[f] = fmaf(-m, s, be[f]);
    }
    __syncthreads();
    int i = blockIdx.x * blockDim.x + threadIdx.x;   // one uint4 (8 halves) each
    if (i >= NN * 8) return;
    int c8 = (i & 7) * 8;
    float4 a = ((const float4*)in)[2 * i];
    float4 b = ((const float4*)in)[2 * i + 1];
    a.x = fmaxf(fmaf(a.x, sc[c8 + 0], sh[c8 + 0]), 0.f);
    a.y = fmaxf(fmaf(a.y, sc[c8 + 1], sh[c8 + 1]), 0.f);
    a.z = fmaxf(fmaf(a.z, sc[c8 + 2], sh[c8 + 2]), 0.f);
    a.w = fmaxf(fmaf(a.w, sc[c8 + 3], sh[c8 + 3]), 0.f);
    b.x = fmaxf(fmaf(b.x, sc[c8 + 4], sh[c8 + 4]), 0.f);
    b.y = fmaxf(fmaf(b.y, sc[c8 + 5], sh[c8 + 5]), 0.f);
    b.z = fmaxf(fmaf(b.z, sc[c8 + 6], sh[c8 + 6]), 0.f);
    b.w = fmaxf(fmaf(b.w, sc[c8 + 7], sh[c8 + 7]), 0.f);
    __half2 h0 = __floats2half2_rn(a.x, a.y);
    __half2 h1 = __floats2half2_rn(a.z, a.w);
    __half2 h2 = __floats2half2_rn(b.x, b.y);
    __half2 h3 = __floats2half2_rn(b.z, b.w);
    uint4 o;
    o.x = *(unsigned*)&h0; o.y = *(unsigned*)&h1;
    o.z = *(unsigned*)&h2; o.w = *(unsigned*)&h3;
    outh[i] = o;
}

// -------------------- fused pool + head --------------------
__global__ void pool_head(const float* __restrict__ h, const int* __restrict__ goff,
                          const float* __restrict__ Wl1, const float* __restrict__ bl1,
                          const float* __restrict__ Wl2, const float* __restrict__ bl2,
                          float* __restrict__ out) {
    __shared__ float sp[64], sz[64];
    int g = blockIdx.x, t = threadIdx.x;
    int beg = goff[g], end = goff[g + 1];
    float s = 0.f;
    for (int n = beg; n < end; ++n) s += h[(size_t)n * 64 + t];
    float c = fmaxf((float)(end - beg), 1.f);
    sp[t] = s / c;
    __syncthreads();
    float z = bl1[t];
#pragma unroll 8
    for (int k = 0; k < 64; k++) z = fmaf(sp[k], Wl1[k * 64 + t], z);
    sz[t] = fmaxf(z, 0.f);
    __syncthreads();
    if (t < 6) {
        float o = bl2[t];
#pragma unroll 8
        for (int k = 0; k < 64; k++) o = fmaf(sz[k], Wl2[k * 6 + t], o);
        out[g * 6 + t] = o;
    }
}

// -------------------- launch --------------------
extern "C" void kernel_launch(void* const* d_in, const int* in_sizes, int n_in,
                              void* d_out, int out_size) {
    const float* x     = (const float*)d_in[0];
    const int*   ei    = (const int*)d_in[1];
    const float* ew    = (const float*)d_in[2];
    const int*   batch = (const int*)d_in[3];
    const float *Wrel0 = (const float*)d_in[4],  *Wroot0 = (const float*)d_in[5],  *b0 = (const float*)d_in[6];
    const float *Wrel1 = (const float*)d_in[7],  *Wroot1 = (const float*)d_in[8],  *b1 = (const float*)d_in[9];
    const float *Wrel2 = (const float*)d_in[10], *Wroot2 = (const float*)d_in[11], *b2 = (const float*)d_in[12];
    const float *g0 = (const float*)d_in[13], *be0 = (const float*)d_in[14];
    const float *g1 = (const float*)d_in[15], *be1 = (const float*)d_in[16];
    const float *Wl1 = (const float*)d_in[17], *bl1 = (const float*)d_in[18];
    const float *Wl2 = (const float*)d_in[19], *bl2 = (const float*)d_in[20];
    float* out = (float*)d_out;

    const int* src = ei;
    const int* dst = ei + EE;

    float *pA, *pB, *pX, *pStats;
    uint4* pH;
    int *pOff, *pCur, *pBsum, *pGoff;
    int2* pEpack;
    cudaGetSymbolAddress((void**)&pA, g_A);
    cudaGetSymbolAddress((void**)&pB, g_B);
    cudaGetSymbolAddress((void**)&pH, g_H);
    cudaGetSymbolAddress((void**)&pX, g_xpad);
    cudaGetSymbolAddress((void**)&pStats, g_stats);
    cudaGetSymbolAddress((void**)&pOff, g_off);
    cudaGetSymbolAddress((void**)&pCur, g_cur);
    cudaGetSymbolAddress((void**)&pBsum, g_bsum);
    cudaGetSymbolAddress((void**)&pGoff, g_goff);
    cudaGetSymbolAddress((void**)&pEpack, g_epack);

    const int smem64 = 64 * 66 * 4 * 2 + 32 * 64 * 8 * 2 + 128 * 4;  // 67072 B
    const int smem9  = (64 * 17 * 2 + 9 * 64 * 2 + 128) * (int)sizeof(float);
    cudaFuncSetAttribute((const void*)node_update64<true>,
                         cudaFuncAttributeMaxDynamicSharedMemorySize, smem64);
    cudaFuncSetAttribute((const void*)node_update64<false>,
                         cudaFuncAttributeMaxDynamicSharedMemorySize, smem64);

    const int NB = (NN + 63) / 64;
    const int SCAN_BLOCKS = (NN + 1 + 1023) / 1024;

    // ---- CSR build + prep ----
    cudaMemsetAsync(pOff, 0, (NN + 1) * sizeof(int));
    prep<<<(EE + 255) / 256, 256>>>(x, pX, dst, pOff, batch, pGoff);
    scan1<<<SCAN_BLOCKS, 1024>>>(pOff, pBsum);
    scan3f<<<SCAN_BLOCKS, 1024>>>(pOff, pBsum, pCur);
    place_kernel<<<(EE + 511) / 512, 512>>>(src, dst, ew, pCur, pEpack);

    // ---- layer 0 (K=9 in padded-16 space, fp32) ----
    agg_csr4<<<(NN + 63) / 64, 256>>>(pX, pOff, pEpack, pA, pStats);
    node_update9<<<NB, 128, smem9>>>(pA, pX, Wrel0, Wroot0, b0, pB, pStats);
    bn_act_h<<<(NN * 8 + 255) / 256, 256>>>(pB, pStats, g0, be0, pH);

    // ---- layer 1 (fp16 gather) ----
    agg_csr_h<<<(NN + 31) / 32, 256>>>(pH, pOff, pEpack, pA, pStats);
    node_update64<true><<<NB, 128, smem64>>>(pA, pH, Wrel1, Wroot1, b1, pB, pStats);
    bn_act_h<<<(NN * 8 + 255) / 256, 256>>>(pB, pStats, g1, be1, pH);

    // ---- layer 2 (fp16 gather, no BN) ----
    agg_csr_h<<<(NN + 31) / 32, 256>>>(pH, pOff, pEpack, pA, nullptr);
    node_update64<false><<<NB, 128, smem64>>>(pA, pH, Wrel2, Wroot2, b2, pB, nullptr);

    // ---- fused pool + head ----
    pool_head<<<GG, 64>>>(pB, pGoff, Wl1, bl1, Wl2, bl2, out);
}

// round 6
// speedup vs baseline: 1.7900x; 1.0087x over previous
#include <cuda_runtime.h>
#include <cuda_fp16.h>

#define NN 100000
#define EE 1600000
#define GG 1024

typedef unsigned long long ull;

// -------------------- device scratch --------------------
__device__ float g_A[(size_t)NN * 64];     // layer-2 aggregation output (fp32)
__device__ float g_B[(size_t)NN * 64];     // raw layer outputs (fp32)
__device__ uint4 g_H[(size_t)NN * 8];      // activated features fp16 (64 halves/node)
__device__ float g_xpad[(size_t)NN * 16];
__device__ int   g_off[NN + 1];
__device__ int   g_cur[NN];
__device__ int   g_bsum[128];
__device__ int2  g_epack[EE];
__device__ int   g_goff[GG + 1];
__device__ float g_stats[256];             // [0:128) layer0, [128:256) layer1

__device__ __forceinline__ void fma2(ull& d, ull a, ull b) {
    asm("fma.rn.f32x2 %0, %1, %2, %0;" : "+l"(d) : "l"(a), "l"(b));
}
__device__ __forceinline__ float2 unpack2(ull v) {
    float2 r; asm("mov.b64 {%0,%1}, %2;" : "=f"(r.x), "=f"(r.y) : "l"(v)); return r;
}
__device__ __forceinline__ ull pack2(float lo, float hi) {
    ull r; asm("mov.b64 %0, {%1,%2};" : "=l"(r) : "f"(lo), "f"(hi)); return r;
}

// -------------------- fused prep: hist + xpad + graph bounds --------------------
__global__ void prep(const float* __restrict__ x, float* __restrict__ xp,
                     const int* __restrict__ dst, int* __restrict__ off,
                     const int* __restrict__ batch, int* __restrict__ goff) {
    int i = blockIdx.x * blockDim.x + threadIdx.x;
    if (i < EE) atomicAdd(&off[dst[i] + 1], 1);
    if (i < NN * 16) { int n = i >> 4, c = i & 15; xp[i] = (c < 9) ? x[n * 9 + c] : 0.f; }
    if (i < NN) {
        int bi = batch[i];
        if (i == 0) { for (int g = 0; g <= bi; g++) goff[g] = 0; }
        else { int bp = batch[i - 1]; for (int g = bp + 1; g <= bi; g++) goff[g] = i; }
        if (i == NN - 1) { for (int g = bi + 1; g <= GG; g++) goff[g] = NN; }
    }
}

// -------------------- scan --------------------
__global__ void scan1(int* __restrict__ off, int* __restrict__ bsum) {
    __shared__ int ws[32];
    int g = blockIdx.x * 1024 + threadIdx.x;
    int v = (g <= NN) ? off[g] : 0;
    int lane = threadIdx.x & 31;
#pragma unroll
    for (int d = 1; d < 32; d <<= 1) { int t = __shfl_up_sync(~0u, v, d); if (lane >= d) v += t; }
    if (lane == 31) ws[threadIdx.x >> 5] = v;
    __syncthreads();
    if (threadIdx.x < 32) {
        int t = ws[threadIdx.x];
#pragma unroll
        for (int d = 1; d < 32; d <<= 1) { int u = __shfl_up_sync(~0u, t, d); if (threadIdx.x >= d) t += u; }
        ws[threadIdx.x] = t;
    }
    __syncthreads();
    if (threadIdx.x >= 32) v += ws[(threadIdx.x >> 5) - 1];
    if (g <= NN) off[g] = v;
    if (threadIdx.x == 1023) bsum[blockIdx.x] = v;
}

__global__ void scan3f(int* __restrict__ off, const int* __restrict__ bsum, int* __restrict__ cur) {
    __shared__ int red[32];
    __shared__ int sadd;
    int t = threadIdx.x;
    int v = (t < blockIdx.x) ? bsum[t] : 0;
#pragma unroll
    for (int d = 16; d; d >>= 1) v += __shfl_down_sync(~0u, v, d);
    if ((t & 31) == 0) red[t >> 5] = v;
    __syncthreads();
    if (t == 0) { int r = 0; for (int w = 0; w < 32; w++) r += red[w]; sadd = r; }
    __syncthreads();
    int g = blockIdx.x * 1024 + t;
    if (g > NN) return;
    int val = off[g] + sadd;
    off[g] = val;
    if (g < NN) cur[g] = val;
}

__global__ void place_kernel(const int* __restrict__ src, const int* __restrict__ dst,
                             const float* __restrict__ ew, int* __restrict__ cur,
                             int2* __restrict__ epack) {
    int e = blockIdx.x * blockDim.x + threadIdx.x;
    if (e >= EE) return;
    int p = atomicAdd(&cur[dst[e]], 1);
    epack[p] = make_int2(src[e], __float_as_int(ew[e]));
}

// -------------------- layer-0 CSR aggregation (fp32, 16-wide padded) ------------
__global__ void __launch_bounds__(256) agg_csr4(
    const float* __restrict__ h, const int* __restrict__ rowptr,
    const int2* __restrict__ epack, float* __restrict__ agg, float* __restrict__ stats) {
    if (blockIdx.x == 0) stats[threadIdx.x] = 0.f;   // zero both stats banks (256 floats)
    int node = blockIdx.x * 64 + (threadIdx.x >> 2);
    int lane = threadIdx.x & 3;
    if (node >= NN) return;
    int beg = rowptr[node], end = rowptr[node + 1];
    float4 acc = make_float4(0.f, 0.f, 0.f, 0.f);
    for (int i = beg; i < end; ++i) {
        int2 ep = epack[i];
        float w = __int_as_float(ep.y);
        float4 v = ((const float4*)h)[(size_t)ep.x * 4 + lane];
        acc.x = fmaf(v.x, w, acc.x);
        acc.y = fmaf(v.y, w, acc.y);
        acc.z = fmaf(v.z, w, acc.z);
        acc.w = fmaf(v.w, w, acc.w);
    }
    ((float4*)agg)[(size_t)node * 4 + lane] = acc;
}

// -------------------- layer-2 CSR aggregation, fp16 rows --------------------
__device__ __forceinline__ void accum8(float* acc, uint4 r, float w) {
    __half2* hp = (__half2*)&r;
#pragma unroll
    for (int j = 0; j < 4; j++) {
        float2 f = __half22float2(hp[j]);
        acc[2 * j]     = fmaf(f.x, w, acc[2 * j]);
        acc[2 * j + 1] = fmaf(f.y, w, acc[2 * j + 1]);
    }
}

__global__ void __launch_bounds__(256) agg_csr_h(
    const uint4* __restrict__ h, const int* __restrict__ rowptr,
    const int2* __restrict__ epack, float* __restrict__ agg) {
    int node = blockIdx.x * 32 + (threadIdx.x >> 3);
    int lane = threadIdx.x & 7;
    if (node >= NN) return;
    int beg = rowptr[node], end = rowptr[node + 1];
    float acc[8];
#pragma unroll
    for (int j = 0; j < 8; j++) acc[j] = 0.f;
    int i = beg;
    for (; i + 1 < end; i += 2) {
        int2 e0 = epack[i], e1 = epack[i + 1];
        uint4 r0 = h[(size_t)e0.x * 8 + lane];
        uint4 r1 = h[(size_t)e1.x * 8 + lane];
        accum8(acc, r0, __int_as_float(e0.y));
        accum8(acc, r1, __int_as_float(e1.y));
    }
    if (i < end) {
        int2 e0 = epack[i];
        uint4 r0 = h[(size_t)e0.x * 8 + lane];
        accum8(acc, r0, __int_as_float(e0.y));
    }
    float* dstp = &agg[(size_t)node * 64 + lane * 8];
    *(float4*)dstp       = make_float4(acc[0], acc[1], acc[2], acc[3]);
    *(float4*)(dstp + 4) = make_float4(acc[4], acc[5], acc[6], acc[7]);
}

// -------------------- layer-0 node update (K=9, scalar) --------------------
__global__ void __launch_bounds__(128) node_update9(
    const float* __restrict__ Ag, const float* __restrict__ Xin,
    const float* __restrict__ Wrel, const float* __restrict__ Wroot,
    const float* __restrict__ bias, float* __restrict__ Out, float* stats) {
    constexpr int K = 9, PAD = 17, C4 = 4;
    extern __shared__ float sm[];
    float* sA   = sm;
    float* sX   = sA + 64 * PAD;
    float* sWr  = sX + 64 * PAD;
    float* sWo  = sWr + K * 64;
    float* sSum = sWo + K * 64;
    float* sSq  = sSum + 64;

    const int tid = threadIdx.x;
    const int base = blockIdx.x * 64;

    for (int i = tid; i < K * 16; i += 128) {
        ((float4*)sWr)[i] = ((const float4*)Wrel)[i];
        ((float4*)sWo)[i] = ((const float4*)Wroot)[i];
    }
    for (int i = tid; i < 64 * C4; i += 128) {
        int r = i / C4, c = i - r * C4;
        int n = base + r;
        float4 va = make_float4(0.f, 0.f, 0.f, 0.f), vx = va;
        if (n < NN) {
            va = *(const float4*)&Ag[(size_t)n * 16 + c * 4];
            vx = *(const float4*)&Xin[(size_t)n * 16 + c * 4];
        }
        int o = r * PAD + c * 4;
        sA[o] = va.x; sA[o + 1] = va.y; sA[o + 2] = va.z; sA[o + 3] = va.w;
        sX[o] = vx.x; sX[o + 1] = vx.y; sX[o + 2] = vx.z; sX[o + 3] = vx.w;
    }
    if (tid < 64) { sSum[tid] = 0.f; sSq[tid] = 0.f; }
    __syncthreads();

    const int fg = (tid & 7) * 8;
    const int ng = (tid >> 3) * 4;

    float acc[4][8];
#pragma unroll
    for (int i = 0; i < 4; i++)
#pragma unroll
        for (int j = 0; j < 8; j++) acc[i][j] = 0.f;

#pragma unroll
    for (int k = 0; k < K; ++k) {
        float a[4], xv[4];
#pragma unroll
        for (int i = 0; i < 4; i++) {
            a[i]  = sA[(ng + i) * PAD + k];
            xv[i] = sX[(ng + i) * PAD + k];
        }
        float wr[8], wo[8];
        *(float4*)&wr[0] = *(const float4*)&sWr[k * 64 + fg];
        *(float4*)&wr[4] = *(const float4*)&sWr[k * 64 + fg + 4];
        *(float4*)&wo[0] = *(const float4*)&sWo[k * 64 + fg];
        *(float4*)&wo[4] = *(const float4*)&sWo[k * 64 + fg + 4];
#pragma unroll
        for (int i = 0; i < 4; i++)
#pragma unroll
            for (int j = 0; j < 8; j++)
                acc[i][j] = fmaf(xv[i], wo[j], fmaf(a[i], wr[j], acc[i][j]));
    }

    float bz[8];
    *(float4*)&bz[0] = *(const float4*)&bias[fg];
    *(float4*)&bz[4] = *(const float4*)&bias[fg + 4];

    float s[8], q[8];
#pragma unroll
    for (int j = 0; j < 8; j++) { s[j] = 0.f; q[j] = 0.f; }

#pragma unroll
    for (int i = 0; i < 4; i++) {
        int n = base + ng + i;
        if (n < NN) {
            float o[8];
#pragma unroll
            for (int j = 0; j < 8; j++) o[j] = acc[i][j] + bz[j];
            *(float4*)&Out[(size_t)n * 64 + fg]     = make_float4(o[0], o[1], o[2], o[3]);
            *(float4*)&Out[(size_t)n * 64 + fg + 4] = make_float4(o[4], o[5], o[6], o[7]);
#pragma unroll
            for (int j = 0; j < 8; j++) { s[j] += o[j]; q[j] += o[j] * o[j]; }
        }
    }
#pragma unroll
    for (int j = 0; j < 8; j++) {
        atomicAdd(&sSum[fg + j], s[j]);
        atomicAdd(&sSq[fg + j], q[j]);
    }
    __syncthreads();
    if (tid < 64) {
        atomicAdd(&stats[tid], sSum[tid]);
        atomicAdd(&stats[64 + tid], sSq[tid]);
    }
}

// -------------------- fused layer-1: CSR gather + f32x2 GEMM + stats ------------
// 256 threads, 64-node tile. Gather phase: 8 lanes/node, 2 passes of 32 nodes,
// fp32 accumulate into sA. GEMM phase: each thread 2 nodes x 8 features.
__global__ void __launch_bounds__(256) fused_nu64(
    const uint4* __restrict__ Xh, const int* __restrict__ rowptr,
    const int2* __restrict__ epack,
    const float* __restrict__ Wrel, const float* __restrict__ Wroot,
    const float* __restrict__ bias, float* __restrict__ Out, float* stats) {
    constexpr int PAD = 68;
    extern __shared__ float sm[];
    float* sA   = sm;                      // 64*68
    float* sX   = sA + 64 * PAD;           // 64*68
    ull*   sWr  = (ull*)(sX + 64 * PAD);   // 32 k2 x 64 f
    ull*   sWo  = sWr + 32 * 64;
    float* sSum = (float*)(sWo + 32 * 64);
    float* sSq  = sSum + 64;

    const int tid = threadIdx.x;
    const int base = blockIdx.x * 64;

    // stage packed weights
    for (int idx = tid; idx < 32 * 16; idx += 256) {
        int k2 = idx >> 4, c4 = idx & 15;
        float4 r0 = ((const float4*)Wrel)[(2 * k2) * 16 + c4];
        float4 r1 = ((const float4*)Wrel)[(2 * k2 + 1) * 16 + c4];
        ull* p = &sWr[k2 * 64 + c4 * 4];
        p[0] = pack2(r0.x, r1.x); p[1] = pack2(r0.y, r1.y);
        p[2] = pack2(r0.z, r1.z); p[3] = pack2(r0.w, r1.w);
        r0 = ((const float4*)Wroot)[(2 * k2) * 16 + c4];
        r1 = ((const float4*)Wroot)[(2 * k2 + 1) * 16 + c4];
        p = &sWo[k2 * 64 + c4 * 4];
        p[0] = pack2(r0.x, r1.x); p[1] = pack2(r0.y, r1.y);
        p[2] = pack2(r0.z, r1.z); p[3] = pack2(r0.w, r1.w);
    }
    // stage Xin (fp16 -> fp32)
    for (int i = tid; i < 64 * 8; i += 256) {
        int r = i >> 3, c = i & 7;
        int n = base + r;
        uint4 v = make_uint4(0u, 0u, 0u, 0u);
        if (n < NN) v = Xh[(size_t)n * 8 + c];
        __half2* hp = (__half2*)&v;
        float* o = &sX[r * PAD + c * 8];
#pragma unroll
        for (int j = 0; j < 4; j++) {
            float2 f = __half22float2(hp[j]);
            o[2 * j] = f.x; o[2 * j + 1] = f.y;
        }
    }
    // gather phase: aggregate edges into sA
#pragma unroll
    for (int pass = 0; pass < 2; ++pass) {
        int nl = pass * 32 + (tid >> 3);
        int lane = tid & 7;
        int node = base + nl;
        float acc[8];
#pragma unroll
        for (int j = 0; j < 8; j++) acc[j] = 0.f;
        if (node < NN) {
            int beg = rowptr[node], end = rowptr[node + 1];
            int i = beg;
            for (; i + 1 < end; i += 2) {
                int2 e0 = epack[i], e1 = epack[i + 1];
                uint4 r0 = Xh[(size_t)e0.x * 8 + lane];
                uint4 r1 = Xh[(size_t)e1.x * 8 + lane];
                accum8(acc, r0, __int_as_float(e0.y));
                accum8(acc, r1, __int_as_float(e1.y));
            }
            if (i < end) {
                int2 e0 = epack[i];
                uint4 r0 = Xh[(size_t)e0.x * 8 + lane];
                accum8(acc, r0, __int_as_float(e0.y));
            }
        }
        float* o = &sA[nl * PAD + lane * 8];
#pragma unroll
        for (int j = 0; j < 8; j++) o[j] = acc[j];
    }
    if (tid < 64) { sSum[tid] = 0.f; sSq[tid] = 0.f; }
    __syncthreads();

    const int f0 = (tid & 7) * 2;
    const int ng = (tid >> 3) * 2;   // 2 nodes per thread

    ull acc2[2][8];
#pragma unroll
    for (int i = 0; i < 2; i++)
#pragma unroll
        for (int j = 0; j < 8; j++) acc2[i][j] = 0ull;

#pragma unroll 2
    for (int k2 = 0; k2 < 32; ++k2) {
        ull av[2], xv[2];
#pragma unroll
        for (int i = 0; i < 2; i++) {
            av[i] = *(const ull*)&sA[(ng + i) * PAD + 2 * k2];
            xv[i] = *(const ull*)&sX[(ng + i) * PAD + 2 * k2];
        }
#pragma unroll
        for (int c = 0; c < 4; c++) {
            ulonglong2 wr = *(const ulonglong2*)&sWr[k2 * 64 + f0 + 16 * c];
            ulonglong2 wo = *(const ulonglong2*)&sWo[k2 * 64 + f0 + 16 * c];
#pragma unroll
            for (int i = 0; i < 2; i++) {
                fma2(acc2[i][2 * c],     av[i], wr.x);
                fma2(acc2[i][2 * c + 1], av[i], wr.y);
                fma2(acc2[i][2 * c],     xv[i], wo.x);
                fma2(acc2[i][2 * c + 1], xv[i], wo.y);
            }
        }
    }

    float bz[8];
#pragma unroll
    for (int c = 0; c < 4; c++) {
        float2 b2 = *(const float2*)&bias[f0 + 16 * c];
        bz[2 * c] = b2.x; bz[2 * c + 1] = b2.y;
    }

    float s[8], q[8];
#pragma unroll
    for (int j = 0; j < 8; j++) { s[j] = 0.f; q[j] = 0.f; }

#pragma unroll
    for (int i = 0; i < 2; i++) {
        int n = base + ng + i;
        if (n < NN) {
#pragma unroll
            for (int c = 0; c < 4; c++) {
                float2 e0 = unpack2(acc2[i][2 * c]);
                float2 e1 = unpack2(acc2[i][2 * c + 1]);
                float o0 = e0.x + e0.y + bz[2 * c];
                float o1 = e1.x + e1.y + bz[2 * c + 1];
                *(float2*)&Out[(size_t)n * 64 + f0 + 16 * c] = make_float2(o0, o1);
                s[2 * c] += o0; q[2 * c] += o0 * o0;
                s[2 * c + 1] += o1; q[2 * c + 1] += o1 * o1;
            }
        }
    }
#pragma unroll
    for (int c = 0; c < 4; c++) {
        atomicAdd(&sSum[f0 + 16 * c],     s[2 * c]);
        atomicAdd(&sSum[f0 + 16 * c + 1], s[2 * c + 1]);
        atomicAdd(&sSq[f0 + 16 * c],      q[2 * c]);
        atomicAdd(&sSq[f0 + 16 * c + 1],  q[2 * c + 1]);
    }
    __syncthreads();
    if (tid < 64) {
        atomicAdd(&stats[tid], sSum[tid]);
        atomicAdd(&stats[64 + tid], sSq[tid]);
    }
}

// -------------------- BN finalize + apply + ReLU + fp16 convert (fused) --------
__global__ void __launch_bounds__(256) bn_act_h(
    const float* __restrict__ in, const float* __restrict__ stats,
    const float* __restrict__ g, const float* __restrict__ be,
    uint4* __restrict__ outh) {
    __shared__ float sc[64], sh[64];
    if (threadIdx.x < 64) {
        int f = threadIdx.x;
        const float inv = 1.f / (float)NN;
        float m = stats[f] * inv;
        float var = stats[64 + f] * inv - m * m;
        float s = g[f] * rsqrtf(var + 1e-5f);
        sc[f] = s;
        sh[f] = fmaf(-m, s, be[f]);
    }
    __syncthreads();
    int i = blockIdx.x * blockDim.x + threadIdx.x;
    if (i >= NN * 8) return;
    int c8 = (i & 7) * 8;
    float4 a = ((const float4*)in)[2 * i];
    float4 b = ((const float4*)in)[2 * i + 1];
    a.x = fmaxf(fmaf(a.x, sc[c8 + 0], sh[c8 + 0]), 0.f);
    a.y = fmaxf(fmaf(a.y, sc[c8 + 1], sh[c8 + 1]), 0.f);
    a.z = fmaxf(fmaf(a.z, sc[c8 + 2], sh[c8 + 2]), 0.f);
    a.w = fmaxf(fmaf(a.w, sc[c8 + 3], sh[c8 + 3]), 0.f);
    b.x = fmaxf(fmaf(b.x, sc[c8 + 4], sh[c8 + 4]), 0.f);
    b.y = fmaxf(fmaf(b.y, sc[c8 + 5], sh[c8 + 5]), 0.f);
    b.z = fmaxf(fmaf(b.z, sc[c8 + 6], sh[c8 + 6]), 0.f);
    b.w = fmaxf(fmaf(b.w, sc[c8 + 7], sh[c8 + 7]), 0.f);
    __half2 h0 = __floats2half2_rn(a.x, a.y);
    __half2 h1 = __floats2half2_rn(a.z, a.w);
    __half2 h2 = __floats2half2_rn(b.x, b.y);
    __half2 h3 = __floats2half2_rn(b.z, b.w);
    uint4 o;
    o.x = *(unsigned*)&h0; o.y = *(unsigned*)&h1;
    o.z = *(unsigned*)&h2; o.w = *(unsigned*)&h3;
    outh[i] = o;
}

// -------------------- layer-2 pooled GEMM + MLP head (fused) --------------------
// pooled = (sumAgg@W2rel + sumX@W2root + cnt*b2) / max(cnt,1); then head.
__global__ void pool2_head(const float* __restrict__ Ag, const uint4* __restrict__ Xh,
                           const float* __restrict__ W2rel, const float* __restrict__ W2root,
                           const float* __restrict__ b2, const int* __restrict__ goff,
                           const float* __restrict__ Wl1, const float* __restrict__ bl1,
                           const float* __restrict__ Wl2, const float* __restrict__ bl2,
                           float* __restrict__ out) {
    __shared__ float sAg[64], sXp[64], sPool[64], sz[64];
    int g = blockIdx.x, t = threadIdx.x;
    int beg = goff[g], end = goff[g + 1];
    const __half* xh = (const __half*)Xh;
    float sa = 0.f, sx = 0.f;
    for (int n = beg; n < end; ++n) {
        sa += Ag[(size_t)n * 64 + t];
        sx += __half2float(xh[(size_t)n * 64 + t]);
    }
    sAg[t] = sa; sXp[t] = sx;
    __syncthreads();
    float cnt = (float)(end - beg);
    float acc = cnt * b2[t];
#pragma unroll 8
    for (int k = 0; k < 64; k++)
        acc += sAg[k] * W2rel[k * 64 + t] + sXp[k] * W2root[k * 64 + t];
    sPool[t] = acc / fmaxf(cnt, 1.f);
    __syncthreads();
    float z = bl1[t];
#pragma unroll 8
    for (int k = 0; k < 64; k++) z = fmaf(sPool[k], Wl1[k * 64 + t], z);
    sz[t] = fmaxf(z, 0.f);
    __syncthreads();
    if (t < 6) {
        float o = bl2[t];
#pragma unroll 8
        for (int k = 0; k < 64; k++) o = fmaf(sz[k], Wl2[k * 6 + t], o);
        out[g * 6 + t] = o;
    }
}

// -------------------- launch --------------------
extern "C" void kernel_launch(void* const* d_in, const int* in_sizes, int n_in,
                              void* d_out, int out_size) {
    const float* x     = (const float*)d_in[0];
    const int*   ei    = (const int*)d_in[1];
    const float* ew    = (const float*)d_in[2];
    const int*   batch = (const int*)d_in[3];
    const float *Wrel0 = (const float*)d_in[4],  *Wroot0 = (const float*)d_in[5],  *b0 = (const float*)d_in[6];
    const float *Wrel1 = (const float*)d_in[7],  *Wroot1 = (const float*)d_in[8],  *b1 = (const float*)d_in[9];
    const float *Wrel2 = (const float*)d_in[10], *Wroot2 = (const float*)d_in[11], *b2 = (const float*)d_in[12];
    const float *g0 = (const float*)d_in[13], *be0 = (const float*)d_in[14];
    const float *g1 = (const float*)d_in[15], *be1 = (const float*)d_in[16];
    const float *Wl1 = (const float*)d_in[17], *bl1 = (const float*)d_in[18];
    const float *Wl2 = (const float*)d_in[19], *bl2 = (const float*)d_in[20];
    float* out = (float*)d_out;

    const int* src = ei;
    const int* dst = ei + EE;

    float *pA, *pB, *pX, *pStats;
    uint4* pH;
    int *pOff, *pCur, *pBsum, *pGoff;
    int2* pEpack;
    cudaGetSymbolAddress((void**)&pA, g_A);
    cudaGetSymbolAddress((void**)&pB, g_B);
    cudaGetSymbolAddress((void**)&pH, g_H);
    cudaGetSymbolAddress((void**)&pX, g_xpad);
    cudaGetSymbolAddress((void**)&pStats, g_stats);
    cudaGetSymbolAddress((void**)&pOff, g_off);
    cudaGetSymbolAddress((void**)&pCur, g_cur);
    cudaGetSymbolAddress((void**)&pBsum, g_bsum);
    cudaGetSymbolAddress((void**)&pGoff, g_goff);
    cudaGetSymbolAddress((void**)&pEpack, g_epack);

    const int smemF = 64 * 68 * 4 * 2 + 32 * 64 * 8 * 2 + 128 * 4;   // 68096 B
    const int smem9 = (64 * 17 * 2 + 9 * 64 * 2 + 128) * (int)sizeof(float);
    cudaFuncSetAttribute((const void*)fused_nu64,
                         cudaFuncAttributeMaxDynamicSharedMemorySize, smemF);

    const int NB = (NN + 63) / 64;
    const int SCAN_BLOCKS = (NN + 1 + 1023) / 1024;

    // ---- CSR build + prep ----
    cudaMemsetAsync(pOff, 0, (NN + 1) * sizeof(int));
    prep<<<(EE + 255) / 256, 256>>>(x, pX, dst, pOff, batch, pGoff);
    scan1<<<SCAN_BLOCKS, 1024>>>(pOff, pBsum);
    scan3f<<<SCAN_BLOCKS, 1024>>>(pOff, pBsum, pCur);
    place_kernel<<<(EE + 511) / 512, 512>>>(src, dst, ew, pCur, pEpack);

    // ---- layer 0 ----
    agg_csr4<<<(NN + 63) / 64, 256>>>(pX, pOff, pEpack, pA, pStats);
    node_update9<<<NB, 128, smem9>>>(pA, pX, Wrel0, Wroot0, b0, pB, pStats);
    bn_act_h<<<(NN * 8 + 255) / 256, 256>>>(pB, pStats, g0, be0, pH);

    // ---- layer 1 (fused gather + GEMM + stats) ----
    fused_nu64<<<NB, 256, smemF>>>(pH, pOff, pEpack, Wrel1, Wroot1, b1, pB, pStats + 128);
    bn_act_h<<<(NN * 8 + 255) / 256, 256>>>(pB, pStats + 128, g1, be1, pH);

    // ---- layer 2: aggregate only, GEMM commuted past mean-pool ----
    agg_csr_h<<<(NN + 31) / 32, 256>>>(pH, pOff, pEpack, pA);
    pool2_head<<<GG, 64>>>(pA, pH, Wrel2, Wroot2, b2, pGoff, Wl1, bl1, Wl2, bl2, out);
}